// round 2
// baseline (speedup 1.0000x reference)
#include <cuda_runtime.h>
#include <math.h>

#define NNODES 50000
#define NEDGES 1000000
#define NDIM   16
#define EMB    64
#define DOUT   64
#define NHEADS 8
#define EADIM  8
#define SLOPE  0.01f
#define LN_EPS 1e-5f

// ---------------- scratch (device globals; no allocations allowed) ----------------
__device__ __align__(128) float g_x[(size_t)NNODES*EMB];                 // node MLP out
__device__ __align__(128) float g_eaproj[(size_t)9*NEDGES];              // ea . a_edge for 9 layers
__device__ __align__(128) float g_h[(size_t)NHEADS*NNODES*DOUT];         // per-head h = x@W
__device__ __align__(128) float g_hprime[(size_t)NHEADS*NNODES*DOUT];    // per-head aggregate
__device__ __align__(128) float g_h2[(size_t)NNODES*DOUT];               // final-layer h
__device__ __align__(128) float g_hp2[(size_t)NNODES*DOUT];              // final-layer aggregate
__device__ __align__(128) float g_s[(size_t)9*NEDGES];                   // scores -> exp values
__device__ __align__(128) float g_asrc[9*NNODES];
__device__ __align__(128) float g_atgt[9*NNODES];
__device__ __align__(128) float g_denom[9*NNODES];                       // -> reciprocal
__device__ unsigned g_smax[16];
__device__ __align__(128) int g_src[NEDGES];
__device__ __align__(128) int g_tgt[NEDGES];
__device__ int g_flag;

// ---------------- helpers ----------------
__device__ __forceinline__ unsigned encf(float f){
  unsigned u = __float_as_uint(f);
  return (u & 0x80000000u) ? ~u : (u | 0x80000000u);
}
__device__ __forceinline__ float decf(unsigned k){
  return (k & 0x80000000u) ? __uint_as_float(k & 0x7fffffffu) : __uint_as_float(~k);
}
__device__ __forceinline__ float eluf(float x){ return x > 0.f ? x : expm1f(x); }
__device__ __forceinline__ float lrelu(float x){ return x >= 0.f ? x : SLOPE * x; }

// ---------------- index dtype detection + conversion ----------------
__global__ void k_detect(const void* ei){
  const long long* p = (const long long*)ei;
  int is64 = 1;
  for(int i = 0; i < 64; i++){
    long long v = p[i];
    if(v < 0 || v >= 4294967296LL) is64 = 0;
  }
  g_flag = is64;
}

__global__ void k_convert(const void* ei){
  int e = blockIdx.x*blockDim.x + threadIdx.x;
  if(e >= NEDGES) return;
  if(g_flag){
    const long long* p = (const long long*)ei;
    g_src[e] = (int)p[e];
    g_tgt[e] = (int)p[NEDGES + e];
  } else {
    const int* p = (const int*)ei;
    g_src[e] = p[e];
    g_tgt[e] = p[NEDGES + e];
  }
}

__global__ void k_zero(){
  long long i = (long long)blockIdx.x*blockDim.x + threadIdx.x;
  if(i < (long long)NHEADS*NNODES*DOUT) g_hprime[i] = 0.f;
  if(i < (long long)NNODES*DOUT)        g_hp2[i]    = 0.f;
  if(i < 9*NNODES)                      g_denom[i]  = 0.f;
  if(i < 16)                            g_smax[i]   = 0u;
}

// ---------------- node MLP: x = relu(LN(X@w + b)) ----------------
__global__ void k_node_mlp(const float* __restrict__ X, const float* __restrict__ w,
                           const float* __restrict__ b, const float* __restrict__ g,
                           const float* __restrict__ beta){
  __shared__ float sw[NDIM*EMB];
  __shared__ float sb[EMB], sg[EMB], sbt[EMB];
  for(int i = threadIdx.x; i < NDIM*EMB; i += blockDim.x) sw[i] = w[i];
  for(int i = threadIdx.x; i < EMB; i += blockDim.x){ sb[i]=b[i]; sg[i]=g[i]; sbt[i]=beta[i]; }
  __syncthreads();
  int n = blockIdx.x*blockDim.x + threadIdx.x;
  if(n >= NNODES) return;
  float xin[NDIM];
  const float4* px = (const float4*)(X + (size_t)n*NDIM);
  #pragma unroll
  for(int q = 0; q < 4; q++){
    float4 v = px[q];
    xin[q*4+0]=v.x; xin[q*4+1]=v.y; xin[q*4+2]=v.z; xin[q*4+3]=v.w;
  }
  float y[EMB]; float sum = 0.f;
  #pragma unroll
  for(int j = 0; j < EMB; j++){
    float a = sb[j];
    #pragma unroll
    for(int k = 0; k < NDIM; k++) a += xin[k]*sw[k*EMB+j];
    y[j] = a; sum += a;
  }
  float mu = sum * (1.f/EMB);
  float vs = 0.f;
  #pragma unroll
  for(int j = 0; j < EMB; j++){ float d = y[j]-mu; vs += d*d; }
  float inv = rsqrtf(vs*(1.f/EMB) + LN_EPS);
  #pragma unroll
  for(int j = 0; j < EMB; j++){
    float v = (y[j]-mu)*inv*sg[j] + sbt[j];
    g_x[(size_t)n*EMB + j] = fmaxf(v, 0.f);
  }
}

// ---------------- edge MLP + 9 projections (never materialize ea) ----------------
__global__ void k_edge_mlp(const float* __restrict__ EA, const float* __restrict__ w,
                           const float* __restrict__ b, const float* __restrict__ g,
                           const float* __restrict__ beta, const float* __restrict__ gat_a,
                           const float* __restrict__ out_a){
  __shared__ float sw[EADIM*EMB];
  __shared__ float sb[EMB], sg[EMB], sbt[EMB];
  __shared__ float sa[9][EMB];
  for(int i = threadIdx.x; i < EADIM*EMB; i += blockDim.x) sw[i] = w[i];
  for(int i = threadIdx.x; i < EMB; i += blockDim.x){ sb[i]=b[i]; sg[i]=g[i]; sbt[i]=beta[i]; }
  for(int i = threadIdx.x; i < 9*EMB; i += blockDim.x){
    int p = i/EMB, j = i%EMB;
    sa[p][j] = (p < 8) ? gat_a[p*192 + 128 + j] : out_a[128 + j];
  }
  __syncthreads();
  int e = blockIdx.x*blockDim.x + threadIdx.x;
  if(e >= NEDGES) return;
  const float4* pe = (const float4*)(EA + (size_t)e*EADIM);
  float4 a0 = pe[0], a1 = pe[1];
  float xin[EADIM] = {a0.x,a0.y,a0.z,a0.w,a1.x,a1.y,a1.z,a1.w};
  float y[EMB]; float sum = 0.f;
  #pragma unroll
  for(int j = 0; j < EMB; j++){
    float a = sb[j];
    #pragma unroll
    for(int k = 0; k < EADIM; k++) a += xin[k]*sw[k*EMB+j];
    y[j] = a; sum += a;
  }
  float mu = sum*(1.f/EMB);
  float vs = 0.f;
  #pragma unroll
  for(int j = 0; j < EMB; j++){ float d = y[j]-mu; vs += d*d; }
  float inv = rsqrtf(vs*(1.f/EMB) + LN_EPS);
  #pragma unroll
  for(int j = 0; j < EMB; j++)
    y[j] = fmaxf((y[j]-mu)*inv*sg[j] + sbt[j], 0.f);
  #pragma unroll
  for(int p = 0; p < 9; p++){
    float acc = 0.f;
    #pragma unroll
    for(int j = 0; j < EMB; j++) acc += y[j]*sa[p][j];
    g_eaproj[(size_t)p*NEDGES + e] = acc;
  }
}

// ---------------- per-head h = x @ W, fused alpha_src/alpha_tgt ----------------
// block = 256 threads, 16 nodes/block, blockIdx.y = head
__global__ void k_head_h(const float* __restrict__ gat_W, const float* __restrict__ gat_a){
  __shared__ float sx[16*EMB];
  __shared__ float sw[EMB*DOUT];
  int head = blockIdx.y;
  int n0 = blockIdx.x*16;
  int t = threadIdx.x;
  const float* W = gat_W + (size_t)head*EMB*DOUT;
  ((float4*)sx)[t] = ((const float4*)(g_x + (size_t)n0*EMB))[t];
  #pragma unroll
  for(int i = 0; i < 4; i++)
    ((float4*)sw)[t + 256*i] = ((const float4*)W)[t + 256*i];
  __syncthreads();
  int nn = t >> 4;
  int j0 = (t & 15)*4;
  float4 acc = {0.f,0.f,0.f,0.f};
  #pragma unroll
  for(int k = 0; k < EMB; k++){
    float xv = sx[nn*EMB + k];
    float4 wv = *(const float4*)&sw[k*DOUT + j0];
    acc.x += xv*wv.x; acc.y += xv*wv.y; acc.z += xv*wv.z; acc.w += xv*wv.w;
  }
  int n = n0 + nn;
  *(float4*)&g_h[((size_t)head*NNODES + n)*DOUT + j0] = acc;
  const float* a = gat_a + head*192;
  float ps = acc.x*a[j0] + acc.y*a[j0+1] + acc.z*a[j0+2] + acc.w*a[j0+3];
  float pt = acc.x*a[64+j0] + acc.y*a[64+j0+1] + acc.z*a[64+j0+2] + acc.w*a[64+j0+3];
  #pragma unroll
  for(int o = 8; o >= 1; o >>= 1){
    ps += __shfl_xor_sync(0xffffffffu, ps, o);
    pt += __shfl_xor_sync(0xffffffffu, pt, o);
  }
  if((t & 15) == 0){
    g_asrc[head*NNODES + n] = ps;
    g_atgt[head*NNODES + n] = pt;
  }
}

// ---------------- edge scores for 8 heads + global max ----------------
__global__ void k_score(){
  int e = blockIdx.x*blockDim.x + threadIdx.x;
  bool valid = e < NEDGES;
  int src = 0, tgt = 0;
  if(valid){ src = g_src[e]; tgt = g_tgt[e]; }
  float mx[NHEADS];
  #pragma unroll
  for(int h = 0; h < NHEADS; h++){
    float s = -1e30f;
    if(valid){
      s = g_asrc[h*NNODES + src] + g_atgt[h*NNODES + tgt] + g_eaproj[(size_t)h*NEDGES + e];
      s = lrelu(s);
      g_s[(size_t)h*NEDGES + e] = s;
    }
    mx[h] = s;
  }
  #pragma unroll
  for(int h = 0; h < NHEADS; h++){
    float m = mx[h];
    #pragma unroll
    for(int o = 16; o >= 1; o >>= 1) m = fmaxf(m, __shfl_xor_sync(0xffffffffu, m, o));
    if((threadIdx.x & 31) == 0) atomicMax(&g_smax[h], encf(m));
  }
}

__global__ void k_expdenom(){
  int e = blockIdx.x*blockDim.x + threadIdx.x;
  if(e >= NEDGES) return;
  int src = g_src[e];
  #pragma unroll
  for(int h = 0; h < NHEADS; h++){
    float m = decf(g_smax[h]);
    float v = expf(g_s[(size_t)h*NEDGES + e] - m);
    g_s[(size_t)h*NEDGES + e] = v;
    atomicAdd(&g_denom[h*NNODES + src], v);
  }
}

__global__ void k_recip(int off, int cnt){
  int i = blockIdx.x*blockDim.x + threadIdx.x;
  if(i < cnt){
    float d = g_denom[off + i];
    g_denom[off + i] = 1.f/(d + 1e-16f);
  }
}

// ---------------- aggregation: hprime[src] += attn * h[tgt] ----------------
// 16 threads per (edge,head); vectorized red.global.add.v4.f32
__global__ void k_agg(int head_base){
  int h = head_base + blockIdx.z;
  int t = threadIdx.x;
  int e = blockIdx.x*16 + (t >> 4);
  int j0 = (t & 15)*4;
  int src = g_src[e], tgt = g_tgt[e];
  float ev = g_s[(size_t)h*NEDGES + e];
  float rd = g_denom[h*NNODES + src];
  float attn = ev * rd;
  const float* hs = (h < NHEADS) ? (g_h + ((size_t)h*NNODES + tgt)*DOUT)
                                 : (g_h2 + (size_t)tgt*DOUT);
  float4 v = *(const float4*)(hs + j0);
  float* op = (h < NHEADS) ? (g_hprime + ((size_t)h*NNODES + src)*DOUT + j0)
                           : (g_hp2 + (size_t)src*DOUT + j0);
  float vx = attn*v.x, vy = attn*v.y, vz = attn*v.z, vw = attn*v.w;
  asm volatile("red.global.add.v4.f32 [%0], {%1, %2, %3, %4};"
               :: "l"(op), "f"(vx), "f"(vy), "f"(vz), "f"(vw) : "memory");
}

// ---------------- final layer: h2 = elu(elu(hprime_concat)) @ out_W + alphas ----------------
__global__ void k_out_h(const float* __restrict__ out_W, const float* __restrict__ out_a){
  __shared__ float sx[16*EMB];
  __shared__ float sw[EMB*DOUT];
  int n0 = blockIdx.x*16;
  int t = threadIdx.x;
  int nn = t >> 4;
  int j0 = (t & 15)*4;
  float4 acc = {0.f,0.f,0.f,0.f};
  for(int c = 0; c < NHEADS; c++){
    __syncthreads();
    float4 xv4 = ((const float4*)(g_hprime + ((size_t)c*NNODES + n0)*DOUT))[t];
    xv4.x = eluf(eluf(xv4.x)); xv4.y = eluf(eluf(xv4.y));
    xv4.z = eluf(eluf(xv4.z)); xv4.w = eluf(eluf(xv4.w));
    ((float4*)sx)[t] = xv4;
    #pragma unroll
    for(int i = 0; i < 4; i++)
      ((float4*)sw)[t + 256*i] = ((const float4*)(out_W + (size_t)c*EMB*DOUT))[t + 256*i];
    __syncthreads();
    #pragma unroll
    for(int k = 0; k < EMB; k++){
      float xv = sx[nn*EMB + k];
      float4 wv = *(const float4*)&sw[k*DOUT + j0];
      acc.x += xv*wv.x; acc.y += xv*wv.y; acc.z += xv*wv.z; acc.w += xv*wv.w;
    }
  }
  int n = n0 + nn;
  *(float4*)&g_h2[(size_t)n*DOUT + j0] = acc;
  float ps = acc.x*out_a[j0] + acc.y*out_a[j0+1] + acc.z*out_a[j0+2] + acc.w*out_a[j0+3];
  float pt = acc.x*out_a[64+j0] + acc.y*out_a[64+j0+1] + acc.z*out_a[64+j0+2] + acc.w*out_a[64+j0+3];
  #pragma unroll
  for(int o = 8; o >= 1; o >>= 1){
    ps += __shfl_xor_sync(0xffffffffu, ps, o);
    pt += __shfl_xor_sync(0xffffffffu, pt, o);
  }
  if((t & 15) == 0){
    g_asrc[NHEADS*NNODES + n] = ps;
    g_atgt[NHEADS*NNODES + n] = pt;
  }
}

__global__ void k_score2(){
  int e = blockIdx.x*blockDim.x + threadIdx.x;
  bool valid = e < NEDGES;
  float s = -1e30f;
  if(valid){
    int src = g_src[e], tgt = g_tgt[e];
    s = g_asrc[NHEADS*NNODES + src] + g_atgt[NHEADS*NNODES + tgt]
      + g_eaproj[(size_t)NHEADS*NEDGES + e];
    s = lrelu(s);
    g_s[(size_t)NHEADS*NEDGES + e] = s;
  }
  float m = s;
  #pragma unroll
  for(int o = 16; o >= 1; o >>= 1) m = fmaxf(m, __shfl_xor_sync(0xffffffffu, m, o));
  if((threadIdx.x & 31) == 0) atomicMax(&g_smax[NHEADS], encf(m));
}

__global__ void k_expdenom2(){
  int e = blockIdx.x*blockDim.x + threadIdx.x;
  if(e >= NEDGES) return;
  int src = g_src[e];
  float m = decf(g_smax[NHEADS]);
  float v = expf(g_s[(size_t)NHEADS*NEDGES + e] - m);
  g_s[(size_t)NHEADS*NEDGES + e] = v;
  atomicAdd(&g_denom[NHEADS*NNODES + src], v);
}

// ---------------- out = log_softmax(elu(hp2)) ----------------
__global__ void k_logsoftmax(float* __restrict__ out){
  int gid = blockIdx.x*blockDim.x + threadIdx.x;
  int n = gid >> 5;
  int lane = gid & 31;
  if(n >= NNODES) return;
  float v0 = eluf(g_hp2[(size_t)n*DOUT + lane]);
  float v1 = eluf(g_hp2[(size_t)n*DOUT + lane + 32]);
  float m = fmaxf(v0, v1);
  #pragma unroll
  for(int o = 16; o >= 1; o >>= 1) m = fmaxf(m, __shfl_xor_sync(0xffffffffu, m, o));
  float s = expf(v0 - m) + expf(v1 - m);
  #pragma unroll
  for(int o = 16; o >= 1; o >>= 1) s += __shfl_xor_sync(0xffffffffu, s, o);
  float l = logf(s);
  out[(size_t)n*DOUT + lane]      = v0 - m - l;
  out[(size_t)n*DOUT + lane + 32] = v1 - m - l;
}

// ---------------- launcher ----------------
extern "C" void kernel_launch(void* const* d_in, const int* in_sizes, int n_in,
                              void* d_out, int out_size){
  const float *X=0, *EA=0, *w_node=0, *w_edge=0, *gatW=0, *gata=0, *outW=0, *outa=0;
  const void* ei = 0;
  const float* v64[8]; int n64 = 0; int nbig = 0;
  for(int i = 0; i < n_in; i++){
    switch(in_sizes[i]){
      case 800000:  X    = (const float*)d_in[i]; break;
      case 8000000: EA   = (const float*)d_in[i]; break;
      case 2000000: ei   = d_in[i]; break;
      case 1024:    w_node = (const float*)d_in[i]; break;
      case 512:     w_edge = (const float*)d_in[i]; break;
      case 1536:    gata = (const float*)d_in[i]; break;
      case 192:     outa = (const float*)d_in[i]; break;
      case 32768:   if(nbig++ == 0) gatW = (const float*)d_in[i];
                    else            outW = (const float*)d_in[i];
                    break;
      case 64:      if(n64 < 8) v64[n64++] = (const float*)d_in[i]; break;
      default: break;  // matched_car_infra_nodes (1000) unused
    }
  }
  const float* b_node = v64[0]; const float* g_node = v64[1]; const float* beta_node = v64[2];
  const float* b_edge = v64[3]; const float* g_edge = v64[4]; const float* beta_edge = v64[5];

  k_detect<<<1, 1>>>(ei);
  k_convert<<<(NEDGES + 255)/256, 256>>>(ei);
  k_zero<<<(int)(((long long)NHEADS*NNODES*DOUT + 255)/256), 256>>>();
  k_node_mlp<<<(NNODES + 255)/256, 256>>>(X, w_node, b_node, g_node, beta_node);
  k_edge_mlp<<<(NEDGES + 127)/128, 128>>>(EA, w_edge, b_edge, g_edge, beta_edge, gata, outa);
  k_head_h<<<dim3(NNODES/16, NHEADS, 1), 256>>>(gatW, gata);
  k_score<<<(NEDGES + 255)/256, 256>>>();
  k_expdenom<<<(NEDGES + 255)/256, 256>>>();
  k_recip<<<(NHEADS*NNODES + 255)/256, 256>>>(0, NHEADS*NNODES);
  k_agg<<<dim3(NEDGES/16, 1, NHEADS), 256>>>(0);
  k_out_h<<<NNODES/16, 256>>>(outW, outa);
  k_score2<<<(NEDGES + 255)/256, 256>>>();
  k_expdenom2<<<(NEDGES + 255)/256, 256>>>();
  k_recip<<<(NNODES + 255)/256, 256>>>(NHEADS*NNODES, NNODES);
  k_agg<<<dim3(NEDGES/16, 1, 1), 256>>>(NHEADS);
  k_logsoftmax<<<(NNODES*32 + 255)/256, 256>>>((float*)d_out);
}

// round 3
// speedup vs baseline: 1.4184x; 1.4184x over previous
#include <cuda_runtime.h>
#include <math.h>

#define NNODES 50000
#define NEDGES 1000000
#define NDIM   16
#define EMB    64
#define DOUT   64
#define NHEADS 8
#define EADIM  8
#define SLOPE  0.01f
#define LN_EPS 1e-5f

// ---------------- scratch (device globals; no allocations allowed) ----------------
__device__ __align__(128) float g_x[(size_t)NNODES*EMB];
__device__ __align__(128) float g_eap[(size_t)NEDGES*16];      // CSR-ordered edge projections (9 used)
__device__ __align__(128) float g_h[(size_t)NHEADS*NNODES*DOUT];
__device__ __align__(128) float g_hp[(size_t)NHEADS*NNODES*DOUT];
__device__ __align__(128) float g_h2[(size_t)NNODES*DOUT];
__device__ __align__(128) float g_hp2[(size_t)NNODES*DOUT];
__device__ __align__(128) float g_exp[(size_t)9*NEDGES];       // exp(score) in CSR order
__device__ __align__(128) float g_asrc[NNODES*16];
__device__ __align__(128) float g_atgt[NNODES*16];
__device__ __align__(128) float g_rden[NNODES*16];             // 1/(denom+1e-16)
__device__ __align__(128) int g_src[NEDGES];
__device__ __align__(128) int g_tgt[NEDGES];
__device__ __align__(128) int g_tgtc[NEDGES];                  // tgt in CSR order
__device__ __align__(128) int g_inv[NEDGES];                   // orig edge -> CSR pos
__device__ __align__(128) int g_row[NNODES+1];
__device__ __align__(128) int g_cur[NNODES];
__device__ __align__(128) int g_cnt[NNODES];
__device__ int g_flag;

__device__ __forceinline__ float eluf(float x){ return x > 0.f ? x : expm1f(x); }
__device__ __forceinline__ float lrelu(float x){ return x >= 0.f ? x : SLOPE * x; }

// ---------------- index dtype detection ----------------
__global__ void k_detect(const void* ei){
  const long long* p = (const long long*)ei;
  int is64 = 1;
  for(int i = 0; i < 64; i++){
    long long v = p[i];
    if(v < 0 || v >= 4294967296LL) is64 = 0;
  }
  g_flag = is64;
}

__global__ void k_zero_cnt(){
  int i = blockIdx.x*blockDim.x + threadIdx.x;
  if(i < NNODES) g_cnt[i] = 0;
}

// convert + histogram
__global__ void k_convert(const void* ei){
  int e = blockIdx.x*blockDim.x + threadIdx.x;
  if(e >= NEDGES) return;
  int s, t;
  if(g_flag){
    const long long* p = (const long long*)ei;
    s = (int)p[e]; t = (int)p[NEDGES + e];
  } else {
    const int* p = (const int*)ei;
    s = p[e]; t = p[NEDGES + e];
  }
  g_src[e] = s; g_tgt[e] = t;
  atomicAdd(&g_cnt[s], 1);
}

// single-block exclusive scan of g_cnt -> g_row, g_cur
__global__ void k_scan(){
  __shared__ int sh[1024];
  __shared__ int carry;
  int t = threadIdx.x;
  if(t == 0) carry = 0;
  __syncthreads();
  for(int base = 0; base < NNODES; base += 1024){
    int i = base + t;
    int v = (i < NNODES) ? g_cnt[i] : 0;
    sh[t] = v; __syncthreads();
    #pragma unroll
    for(int o = 1; o < 1024; o <<= 1){
      int add = (t >= o) ? sh[t-o] : 0;
      __syncthreads();
      sh[t] += add;
      __syncthreads();
    }
    int excl = carry + sh[t] - v;
    if(i < NNODES){ g_row[i] = excl; g_cur[i] = excl; }
    __syncthreads();
    if(t == 0) carry += sh[1023];
    __syncthreads();
  }
  if(t == 0) g_row[NNODES] = NEDGES;
}

__global__ void k_scatter(){
  int e = blockIdx.x*blockDim.x + threadIdx.x;
  if(e >= NEDGES) return;
  int s = g_src[e];
  int pos = atomicAdd(&g_cur[s], 1);
  g_tgtc[pos] = g_tgt[e];
  g_inv[e] = pos;
}

// ---------------- node MLP: x = relu(LN(X@w + b)) ----------------
__global__ void k_node_mlp(const float* __restrict__ X, const float* __restrict__ w,
                           const float* __restrict__ b, const float* __restrict__ g,
                           const float* __restrict__ beta){
  __shared__ float sw[NDIM*EMB];
  __shared__ float sb[EMB], sg[EMB], sbt[EMB];
  for(int i = threadIdx.x; i < NDIM*EMB; i += blockDim.x) sw[i] = w[i];
  for(int i = threadIdx.x; i < EMB; i += blockDim.x){ sb[i]=b[i]; sg[i]=g[i]; sbt[i]=beta[i]; }
  __syncthreads();
  int n = blockIdx.x*blockDim.x + threadIdx.x;
  if(n >= NNODES) return;
  float xin[NDIM];
  const float4* px = (const float4*)(X + (size_t)n*NDIM);
  #pragma unroll
  for(int q = 0; q < 4; q++){
    float4 v = px[q];
    xin[q*4+0]=v.x; xin[q*4+1]=v.y; xin[q*4+2]=v.z; xin[q*4+3]=v.w;
  }
  float y[EMB]; float sum = 0.f;
  #pragma unroll
  for(int j = 0; j < EMB; j++){
    float a = sb[j];
    #pragma unroll
    for(int k = 0; k < NDIM; k++) a += xin[k]*sw[k*EMB+j];
    y[j] = a; sum += a;
  }
  float mu = sum * (1.f/EMB);
  float vs = 0.f;
  #pragma unroll
  for(int j = 0; j < EMB; j++){ float d = y[j]-mu; vs += d*d; }
  float inv = rsqrtf(vs*(1.f/EMB) + LN_EPS);
  #pragma unroll
  for(int j = 0; j < EMB; j++){
    float v = (y[j]-mu)*inv*sg[j] + sbt[j];
    g_x[(size_t)n*EMB + j] = fmaxf(v, 0.f);
  }
}

// ---------------- edge MLP + 9 projections, written in CSR order ----------------
__global__ void k_edge_mlp(const float* __restrict__ EA, const float* __restrict__ w,
                           const float* __restrict__ b, const float* __restrict__ g,
                           const float* __restrict__ beta, const float* __restrict__ gat_a,
                           const float* __restrict__ out_a){
  __shared__ float sw[EADIM*EMB];
  __shared__ float sb[EMB], sg[EMB], sbt[EMB];
  __shared__ float sa[9][EMB];
  for(int i = threadIdx.x; i < EADIM*EMB; i += blockDim.x) sw[i] = w[i];
  for(int i = threadIdx.x; i < EMB; i += blockDim.x){ sb[i]=b[i]; sg[i]=g[i]; sbt[i]=beta[i]; }
  for(int i = threadIdx.x; i < 9*EMB; i += blockDim.x){
    int p = i/EMB, j = i%EMB;
    sa[p][j] = (p < 8) ? gat_a[p*192 + 128 + j] : out_a[128 + j];
  }
  __syncthreads();
  int e = blockIdx.x*blockDim.x + threadIdx.x;
  if(e >= NEDGES) return;
  const float4* pe = (const float4*)(EA + (size_t)e*EADIM);
  float4 a0 = pe[0], a1 = pe[1];
  float xin[EADIM] = {a0.x,a0.y,a0.z,a0.w,a1.x,a1.y,a1.z,a1.w};
  float y[EMB]; float sum = 0.f;
  #pragma unroll
  for(int j = 0; j < EMB; j++){
    float a = sb[j];
    #pragma unroll
    for(int k = 0; k < EADIM; k++) a += xin[k]*sw[k*EMB+j];
    y[j] = a; sum += a;
  }
  float mu = sum*(1.f/EMB);
  float vs = 0.f;
  #pragma unroll
  for(int j = 0; j < EMB; j++){ float d = y[j]-mu; vs += d*d; }
  float inv = rsqrtf(vs*(1.f/EMB) + LN_EPS);
  #pragma unroll
  for(int j = 0; j < EMB; j++)
    y[j] = fmaxf((y[j]-mu)*inv*sg[j] + sbt[j], 0.f);
  float pr[9];
  #pragma unroll
  for(int p = 0; p < 9; p++){
    float acc = 0.f;
    #pragma unroll
    for(int j = 0; j < EMB; j++) acc += y[j]*sa[p][j];
    pr[p] = acc;
  }
  size_t pos = (size_t)g_inv[e]*16;
  float4 v0 = {pr[0],pr[1],pr[2],pr[3]};
  float4 v1 = {pr[4],pr[5],pr[6],pr[7]};
  *(float4*)&g_eap[pos]   = v0;
  *(float4*)&g_eap[pos+4] = v1;
  g_eap[pos+8] = pr[8];
}

// ---------------- per-head h = x @ W, fused alpha_src/alpha_tgt ----------------
__global__ void k_head_h(const float* __restrict__ gat_W, const float* __restrict__ gat_a){
  __shared__ float sx[16*EMB];
  __shared__ float sw[EMB*DOUT];
  int head = blockIdx.y;
  int n0 = blockIdx.x*16;
  int t = threadIdx.x;
  const float* W = gat_W + (size_t)head*EMB*DOUT;
  ((float4*)sx)[t] = ((const float4*)(g_x + (size_t)n0*EMB))[t];
  #pragma unroll
  for(int i = 0; i < 4; i++)
    ((float4*)sw)[t + 256*i] = ((const float4*)W)[t + 256*i];
  __syncthreads();
  int nn = t >> 4;
  int j0 = (t & 15)*4;
  float4 acc = {0.f,0.f,0.f,0.f};
  #pragma unroll
  for(int k = 0; k < EMB; k++){
    float xv = sx[nn*EMB + k];
    float4 wv = *(const float4*)&sw[k*DOUT + j0];
    acc.x += xv*wv.x; acc.y += xv*wv.y; acc.z += xv*wv.z; acc.w += xv*wv.w;
  }
  int n = n0 + nn;
  *(float4*)&g_h[((size_t)head*NNODES + n)*DOUT + j0] = acc;
  const float* a = gat_a + head*192;
  float ps = acc.x*a[j0] + acc.y*a[j0+1] + acc.z*a[j0+2] + acc.w*a[j0+3];
  float pt = acc.x*a[64+j0] + acc.y*a[64+j0+1] + acc.z*a[64+j0+2] + acc.w*a[64+j0+3];
  #pragma unroll
  for(int o = 8; o >= 1; o >>= 1){
    ps += __shfl_xor_sync(0xffffffffu, ps, o);
    pt += __shfl_xor_sync(0xffffffffu, pt, o);
  }
  if((t & 15) == 0){
    g_asrc[n*16 + head] = ps;
    g_atgt[n*16 + head] = pt;
  }
}

// ---------------- fused score + exp + denom for 8 heads (warp per node, no atomics) --------
__global__ void k_sed1(){
  int warp = (blockIdx.x*blockDim.x + threadIdx.x) >> 5;
  int lane = threadIdx.x & 31;
  if(warp >= NNODES) return;
  int n = warp;
  int r0 = g_row[n], r1 = g_row[n+1];
  float4 as0 = *(const float4*)&g_asrc[n*16];
  float4 as1 = *(const float4*)&g_asrc[n*16+4];
  float acc[8] = {0.f,0.f,0.f,0.f,0.f,0.f,0.f,0.f};
  for(int pos = r0 + lane; pos < r1; pos += 32){
    int tg = g_tgtc[pos];
    float4 e0 = *(const float4*)&g_eap[(size_t)pos*16];
    float4 e1 = *(const float4*)&g_eap[(size_t)pos*16+4];
    float4 t0 = *(const float4*)&g_atgt[tg*16];
    float4 t1 = *(const float4*)&g_atgt[tg*16+4];
    float ev;
    ev = __expf(lrelu(as0.x + t0.x + e0.x)); g_exp[(size_t)0*NEDGES+pos] = ev; acc[0] += ev;
    ev = __expf(lrelu(as0.y + t0.y + e0.y)); g_exp[(size_t)1*NEDGES+pos] = ev; acc[1] += ev;
    ev = __expf(lrelu(as0.z + t0.z + e0.z)); g_exp[(size_t)2*NEDGES+pos] = ev; acc[2] += ev;
    ev = __expf(lrelu(as0.w + t0.w + e0.w)); g_exp[(size_t)3*NEDGES+pos] = ev; acc[3] += ev;
    ev = __expf(lrelu(as1.x + t1.x + e1.x)); g_exp[(size_t)4*NEDGES+pos] = ev; acc[4] += ev;
    ev = __expf(lrelu(as1.y + t1.y + e1.y)); g_exp[(size_t)5*NEDGES+pos] = ev; acc[5] += ev;
    ev = __expf(lrelu(as1.z + t1.z + e1.z)); g_exp[(size_t)6*NEDGES+pos] = ev; acc[6] += ev;
    ev = __expf(lrelu(as1.w + t1.w + e1.w)); g_exp[(size_t)7*NEDGES+pos] = ev; acc[7] += ev;
  }
  #pragma unroll
  for(int h = 0; h < 8; h++){
    float a = acc[h];
    #pragma unroll
    for(int o = 16; o >= 1; o >>= 1) a += __shfl_xor_sync(0xffffffffu, a, o);
    acc[h] = a;
  }
  if(lane == 0){
    #pragma unroll
    for(int h = 0; h < 8; h++)
      g_rden[n*16 + h] = 1.f/(acc[h] + 1e-16f);
  }
}

// ---------------- CSR aggregation: warp per (node, head), no atomics ----------------
__global__ void k_agg(int head_base){
  int h = head_base + blockIdx.y;
  int warp = (blockIdx.x*blockDim.x + threadIdx.x) >> 5;
  int lane = threadIdx.x & 31;
  if(warp >= NNODES) return;
  int n = warp;
  int r0 = g_row[n], r1 = g_row[n+1];
  float rd = g_rden[n*16 + h];
  const float* __restrict__ hsrc = (h < NHEADS) ? (g_h + (size_t)h*NNODES*DOUT) : g_h2;
  const float* __restrict__ ex = g_exp + (size_t)h*NEDGES;
  float a0 = 0.f, a1 = 0.f;
  int pos = r0;
  for(; pos + 1 < r1; pos += 2){
    int tg0 = g_tgtc[pos];
    int tg1 = g_tgtc[pos+1];
    float w0 = ex[pos]   * rd;
    float w1 = ex[pos+1] * rd;
    const float* p0 = hsrc + (size_t)tg0*DOUT;
    const float* p1 = hsrc + (size_t)tg1*DOUT;
    float x0 = p0[lane], y0 = p0[lane+32];
    float x1 = p1[lane], y1 = p1[lane+32];
    a0 += w0*x0; a1 += w0*y0;
    a0 += w1*x1; a1 += w1*y1;
  }
  if(pos < r1){
    int tg = g_tgtc[pos];
    float w = ex[pos] * rd;
    const float* p = hsrc + (size_t)tg*DOUT;
    a0 += w*p[lane]; a1 += w*p[lane+32];
  }
  float* out = (h < NHEADS) ? (g_hp + ((size_t)h*NNODES + n)*DOUT)
                            : (g_hp2 + (size_t)n*DOUT);
  out[lane]    = a0;
  out[lane+32] = a1;
}

// ---------------- final layer h2 = elu(elu(hp_concat)) @ out_W + alphas ----------------
__global__ void k_out_h(const float* __restrict__ out_W, const float* __restrict__ out_a){
  __shared__ float sx[16*EMB];
  __shared__ float sw[EMB*DOUT];
  int n0 = blockIdx.x*16;
  int t = threadIdx.x;
  int nn = t >> 4;
  int j0 = (t & 15)*4;
  float4 acc = {0.f,0.f,0.f,0.f};
  for(int c = 0; c < NHEADS; c++){
    __syncthreads();
    float4 xv4 = ((const float4*)(g_hp + ((size_t)c*NNODES + n0)*DOUT))[t];
    xv4.x = eluf(eluf(xv4.x)); xv4.y = eluf(eluf(xv4.y));
    xv4.z = eluf(eluf(xv4.z)); xv4.w = eluf(eluf(xv4.w));
    ((float4*)sx)[t] = xv4;
    #pragma unroll
    for(int i = 0; i < 4; i++)
      ((float4*)sw)[t + 256*i] = ((const float4*)(out_W + (size_t)c*EMB*DOUT))[t + 256*i];
    __syncthreads();
    #pragma unroll
    for(int k = 0; k < EMB; k++){
      float xv = sx[nn*EMB + k];
      float4 wv = *(const float4*)&sw[k*DOUT + j0];
      acc.x += xv*wv.x; acc.y += xv*wv.y; acc.z += xv*wv.z; acc.w += xv*wv.w;
    }
  }
  int n = n0 + nn;
  *(float4*)&g_h2[(size_t)n*DOUT + j0] = acc;
  float ps = acc.x*out_a[j0] + acc.y*out_a[j0+1] + acc.z*out_a[j0+2] + acc.w*out_a[j0+3];
  float pt = acc.x*out_a[64+j0] + acc.y*out_a[64+j0+1] + acc.z*out_a[64+j0+2] + acc.w*out_a[64+j0+3];
  #pragma unroll
  for(int o = 8; o >= 1; o >>= 1){
    ps += __shfl_xor_sync(0xffffffffu, ps, o);
    pt += __shfl_xor_sync(0xffffffffu, pt, o);
  }
  if((t & 15) == 0){
    g_asrc[n*16 + 8] = ps;
    g_atgt[n*16 + 8] = pt;
  }
}

// ---------------- score+exp+denom for final layer ----------------
__global__ void k_sed2(){
  int warp = (blockIdx.x*blockDim.x + threadIdx.x) >> 5;
  int lane = threadIdx.x & 31;
  if(warp >= NNODES) return;
  int n = warp;
  int r0 = g_row[n], r1 = g_row[n+1];
  float as2 = g_asrc[n*16 + 8];
  float acc = 0.f;
  for(int pos = r0 + lane; pos < r1; pos += 32){
    int tg = g_tgtc[pos];
    float s = as2 + g_atgt[tg*16 + 8] + g_eap[(size_t)pos*16 + 8];
    float ev = __expf(lrelu(s));
    g_exp[(size_t)8*NEDGES + pos] = ev;
    acc += ev;
  }
  #pragma unroll
  for(int o = 16; o >= 1; o >>= 1) acc += __shfl_xor_sync(0xffffffffu, acc, o);
  if(lane == 0) g_rden[n*16 + 8] = 1.f/(acc + 1e-16f);
}

// ---------------- out = log_softmax(elu(hp2)) ----------------
__global__ void k_logsoftmax(float* __restrict__ out){
  int gid = blockIdx.x*blockDim.x + threadIdx.x;
  int n = gid >> 5;
  int lane = gid & 31;
  if(n >= NNODES) return;
  float v0 = eluf(g_hp2[(size_t)n*DOUT + lane]);
  float v1 = eluf(g_hp2[(size_t)n*DOUT + lane + 32]);
  float m = fmaxf(v0, v1);
  #pragma unroll
  for(int o = 16; o >= 1; o >>= 1) m = fmaxf(m, __shfl_xor_sync(0xffffffffu, m, o));
  float s = expf(v0 - m) + expf(v1 - m);
  #pragma unroll
  for(int o = 16; o >= 1; o >>= 1) s += __shfl_xor_sync(0xffffffffu, s, o);
  float l = logf(s);
  out[(size_t)n*DOUT + lane]      = v0 - m - l;
  out[(size_t)n*DOUT + lane + 32] = v1 - m - l;
}

// ---------------- launcher ----------------
extern "C" void kernel_launch(void* const* d_in, const int* in_sizes, int n_in,
                              void* d_out, int out_size){
  const float *X=0, *EA=0, *w_node=0, *w_edge=0, *gatW=0, *gata=0, *outW=0, *outa=0;
  const void* ei = 0;
  const float* v64[8]; int n64 = 0; int nbig = 0;
  for(int i = 0; i < n_in; i++){
    switch(in_sizes[i]){
      case 800000:  X    = (const float*)d_in[i]; break;
      case 8000000: EA   = (const float*)d_in[i]; break;
      case 2000000: ei   = d_in[i]; break;
      case 1024:    w_node = (const float*)d_in[i]; break;
      case 512:     w_edge = (const float*)d_in[i]; break;
      case 1536:    gata = (const float*)d_in[i]; break;
      case 192:     outa = (const float*)d_in[i]; break;
      case 32768:   if(nbig++ == 0) gatW = (const float*)d_in[i];
                    else            outW = (const float*)d_in[i];
                    break;
      case 64:      if(n64 < 8) v64[n64++] = (const float*)d_in[i]; break;
      default: break;
    }
  }
  const float* b_node = v64[0]; const float* g_node = v64[1]; const float* beta_node = v64[2];
  const float* b_edge = v64[3]; const float* g_edge = v64[4]; const float* beta_edge = v64[5];

  // CSR build
  k_detect<<<1, 1>>>(ei);
  k_zero_cnt<<<(NNODES + 255)/256, 256>>>();
  k_convert<<<(NEDGES + 255)/256, 256>>>(ei);
  k_scan<<<1, 1024>>>();
  k_scatter<<<(NEDGES + 255)/256, 256>>>();

  // MLPs + projections
  k_node_mlp<<<(NNODES + 255)/256, 256>>>(X, w_node, b_node, g_node, beta_node);
  k_edge_mlp<<<(NEDGES + 127)/128, 128>>>(EA, w_edge, b_edge, g_edge, beta_edge, gata, outa);
  k_head_h<<<dim3(NNODES/16, NHEADS, 1), 256>>>(gatW, gata);

  // layer 1: fused score/exp/denom, then CSR aggregation
  k_sed1<<<(NNODES*32 + 255)/256, 256>>>();
  k_agg<<<dim3((NNODES*32 + 255)/256, NHEADS, 1), 256>>>(0);

  // layer 2
  k_out_h<<<NNODES/16, 256>>>(outW, outa);
  k_sed2<<<(NNODES*32 + 255)/256, 256>>>();
  k_agg<<<dim3((NNODES*32 + 255)/256, 1, 1), 256>>>(NHEADS);

  k_logsoftmax<<<(NNODES*32 + 255)/256, 256>>>((float*)d_out);
}

// round 4
// speedup vs baseline: 1.4460x; 1.0195x over previous
#include <cuda_runtime.h>
#include <math.h>

#define NNODES 50000
#define NEDGES 1000000
#define NDIM   16
#define EMB    64
#define DOUT   64
#define NHEADS 8
#define EADIM  8
#define SLOPE  0.01f
#define LN_EPS 1e-5f
#define SCANB  49   // ceil(50000/1024)

// ---------------- scratch ----------------
__device__ __align__(128) float g_x[(size_t)NNODES*EMB];
__device__ __align__(128) float g_eap[(size_t)NEDGES*16];
__device__ __align__(128) float g_h[(size_t)NHEADS*NNODES*DOUT];
__device__ __align__(128) float g_hp[(size_t)NHEADS*NNODES*DOUT];
__device__ __align__(128) float g_h2[(size_t)NNODES*DOUT];
__device__ __align__(128) float g_hp2[(size_t)NNODES*DOUT];
__device__ __align__(128) float g_asrc[NNODES*16];
__device__ __align__(128) float g_atgt[NNODES*16];
__device__ __align__(128) int g_src[NEDGES];
__device__ __align__(128) int g_tgt[NEDGES];
__device__ __align__(128) int g_tgtc[NEDGES];
__device__ __align__(128) int g_inv[NEDGES];
__device__ __align__(128) int g_row[NNODES+1];
__device__ __align__(128) int g_cur[NNODES];
__device__ __align__(128) int g_cnt[NNODES];
__device__ __align__(128) int g_part[64];
__device__ int g_flag;

__device__ __forceinline__ float eluf(float x){ return x > 0.f ? x : expm1f(x); }
__device__ __forceinline__ float lrelu(float x){ return x >= 0.f ? x : SLOPE * x; }

// ---------------- f32x2 packed helpers (Blackwell FFMA2) ----------------
typedef unsigned long long u64t;
__device__ __forceinline__ u64t pack2(float lo, float hi){
  u64t r; asm("mov.b64 %0, {%1,%2};" : "=l"(r) : "f"(lo), "f"(hi)); return r;
}
__device__ __forceinline__ u64t ffma2(u64t a, u64t b, u64t c){
  u64t d; asm("fma.rn.f32x2 %0, %1, %2, %3;" : "=l"(d) : "l"(a), "l"(b), "l"(c)); return d;
}
__device__ __forceinline__ float2 unpack2(u64t v){
  float2 f; asm("mov.b64 {%0,%1}, %2;" : "=f"(f.x), "=f"(f.y) : "l"(v)); return f;
}

// ---------------- index dtype detection ----------------
__global__ void k_detect(const void* ei){
  const long long* p = (const long long*)ei;
  int is64 = 1;
  for(int i = 0; i < 64; i++){
    long long v = p[i];
    if(v < 0 || v >= 4294967296LL) is64 = 0;
  }
  g_flag = is64;
}

__global__ void k_zero_cnt(){
  int i = blockIdx.x*blockDim.x + threadIdx.x;
  if(i < NNODES) g_cnt[i] = 0;
}

__global__ void k_convert(const void* ei){
  int e = blockIdx.x*blockDim.x + threadIdx.x;
  if(e >= NEDGES) return;
  int s, t;
  if(g_flag){
    const long long* p = (const long long*)ei;
    s = (int)p[e]; t = (int)p[NEDGES + e];
  } else {
    const int* p = (const int*)ei;
    s = p[e]; t = p[NEDGES + e];
  }
  g_src[e] = s; g_tgt[e] = t;
  atomicAdd(&g_cnt[s], 1);
}

// ---------------- parallel scan (3 phases) ----------------
__global__ void k_scan1(){
  __shared__ int swarp[32];
  int i = blockIdx.x*1024 + threadIdx.x;
  int lane = threadIdx.x & 31, wid = threadIdx.x >> 5;
  int v = (i < NNODES) ? g_cnt[i] : 0;
  int x = v;
  #pragma unroll
  for(int o = 1; o < 32; o <<= 1){
    int y = __shfl_up_sync(0xffffffffu, x, o);
    if(lane >= o) x += y;
  }
  if(lane == 31) swarp[wid] = x;
  __syncthreads();
  if(wid == 0){
    int s = swarp[lane];
    #pragma unroll
    for(int o = 1; o < 32; o <<= 1){
      int y = __shfl_up_sync(0xffffffffu, s, o);
      if(lane >= o) s += y;
    }
    swarp[lane] = s;
  }
  __syncthreads();
  int base = wid ? swarp[wid-1] : 0;
  int incl = base + x;
  if(i < NNODES) g_row[i] = incl - v;       // exclusive within block
  if(threadIdx.x == 1023) g_part[blockIdx.x] = incl;
}

__global__ void k_scan2(){
  if(threadIdx.x == 0){
    int s = 0;
    for(int i = 0; i < SCANB; i++){ int v = g_part[i]; g_part[i] = s; s += v; }
  }
}

__global__ void k_scan3(){
  int i = blockIdx.x*1024 + threadIdx.x;
  if(i < NNODES){
    int r = g_row[i] + g_part[blockIdx.x];
    g_row[i] = r; g_cur[i] = r;
  }
  if(i == 0) g_row[NNODES] = NEDGES;
}

__global__ void k_scatter(){
  int e = blockIdx.x*blockDim.x + threadIdx.x;
  if(e >= NEDGES) return;
  int s = g_src[e];
  int pos = atomicAdd(&g_cur[s], 1);
  g_tgtc[pos] = g_tgt[e];
  g_inv[e] = pos;
}

// ---------------- node MLP ----------------
__global__ void k_node_mlp(const float* __restrict__ X, const float* __restrict__ w,
                           const float* __restrict__ b, const float* __restrict__ g,
                           const float* __restrict__ beta){
  __shared__ float sw[NDIM*EMB];
  __shared__ float sb[EMB], sg[EMB], sbt[EMB];
  for(int i = threadIdx.x; i < NDIM*EMB; i += blockDim.x) sw[i] = w[i];
  for(int i = threadIdx.x; i < EMB; i += blockDim.x){ sb[i]=b[i]; sg[i]=g[i]; sbt[i]=beta[i]; }
  __syncthreads();
  int n = blockIdx.x*blockDim.x + threadIdx.x;
  if(n >= NNODES) return;
  float xin[NDIM];
  const float4* px = (const float4*)(X + (size_t)n*NDIM);
  #pragma unroll
  for(int q = 0; q < 4; q++){
    float4 v = px[q];
    xin[q*4+0]=v.x; xin[q*4+1]=v.y; xin[q*4+2]=v.z; xin[q*4+3]=v.w;
  }
  u64t xk2[NDIM];
  #pragma unroll
  for(int k = 0; k < NDIM; k++) xk2[k] = pack2(xin[k], xin[k]);
  float y[EMB]; float sum = 0.f;
  #pragma unroll
  for(int jp = 0; jp < EMB/2; jp++){
    u64t acc = pack2(sb[2*jp], sb[2*jp+1]);
    #pragma unroll
    for(int k = 0; k < NDIM; k++)
      acc = ffma2(xk2[k], *(const u64t*)&sw[k*EMB + 2*jp], acc);
    float2 f = unpack2(acc);
    y[2*jp] = f.x; y[2*jp+1] = f.y;
    sum += f.x + f.y;
  }
  float mu = sum * (1.f/EMB);
  float vs = 0.f;
  #pragma unroll
  for(int j = 0; j < EMB; j++){ float d = y[j]-mu; vs += d*d; }
  float inv = rsqrtf(vs*(1.f/EMB) + LN_EPS);
  #pragma unroll
  for(int j = 0; j < EMB; j++){
    float v = (y[j]-mu)*inv*sg[j] + sbt[j];
    g_x[(size_t)n*EMB + j] = fmaxf(v, 0.f);
  }
}

// ---------------- edge MLP + 9 projections (f32x2), CSR-ordered output ----------------
__global__ void k_edge_mlp(const float* __restrict__ EA, const float* __restrict__ w,
                           const float* __restrict__ b, const float* __restrict__ g,
                           const float* __restrict__ beta, const float* __restrict__ gat_a,
                           const float* __restrict__ out_a){
  __shared__ float sw[EADIM*EMB];
  __shared__ float sb[EMB], sg[EMB], sbt[EMB];
  __shared__ float sa[9][EMB];
  for(int i = threadIdx.x; i < EADIM*EMB; i += blockDim.x) sw[i] = w[i];
  for(int i = threadIdx.x; i < EMB; i += blockDim.x){ sb[i]=b[i]; sg[i]=g[i]; sbt[i]=beta[i]; }
  for(int i = threadIdx.x; i < 9*EMB; i += blockDim.x){
    int p = i/EMB, j = i%EMB;
    sa[p][j] = (p < 8) ? gat_a[p*192 + 128 + j] : out_a[128 + j];
  }
  __syncthreads();
  int e = blockIdx.x*blockDim.x + threadIdx.x;
  if(e >= NEDGES) return;
  const float4* pe = (const float4*)(EA + (size_t)e*EADIM);
  float4 a0 = pe[0], a1 = pe[1];
  float xin[EADIM] = {a0.x,a0.y,a0.z,a0.w,a1.x,a1.y,a1.z,a1.w};
  u64t xk2[EADIM];
  #pragma unroll
  for(int k = 0; k < EADIM; k++) xk2[k] = pack2(xin[k], xin[k]);
  float y[EMB]; float sum = 0.f;
  #pragma unroll
  for(int jp = 0; jp < EMB/2; jp++){
    u64t acc = pack2(sb[2*jp], sb[2*jp+1]);
    #pragma unroll
    for(int k = 0; k < EADIM; k++)
      acc = ffma2(xk2[k], *(const u64t*)&sw[k*EMB + 2*jp], acc);
    float2 f = unpack2(acc);
    y[2*jp] = f.x; y[2*jp+1] = f.y;
    sum += f.x + f.y;
  }
  float mu = sum*(1.f/EMB);
  float vs = 0.f;
  #pragma unroll
  for(int j = 0; j < EMB; j++){ float d = y[j]-mu; vs += d*d; }
  float inv = rsqrtf(vs*(1.f/EMB) + LN_EPS);
  u64t y2[EMB/2];
  #pragma unroll
  for(int j = 0; j < EMB; j += 2){
    float v0 = fmaxf((y[j]-mu)*inv*sg[j] + sbt[j], 0.f);
    float v1 = fmaxf((y[j+1]-mu)*inv*sg[j+1] + sbt[j+1], 0.f);
    y2[j/2] = pack2(v0, v1);
  }
  float pr[9];
  #pragma unroll
  for(int p = 0; p < 9; p++){
    u64t acc = 0;  // (0.f,0.f)
    #pragma unroll
    for(int jp = 0; jp < EMB/2; jp++)
      acc = ffma2(y2[jp], *(const u64t*)&sa[p][2*jp], acc);
    float2 f = unpack2(acc);
    pr[p] = f.x + f.y;
  }
  size_t pos = (size_t)g_inv[e]*16;
  float4 v0 = {pr[0],pr[1],pr[2],pr[3]};
  float4 v1 = {pr[4],pr[5],pr[6],pr[7]};
  *(float4*)&g_eap[pos]   = v0;
  *(float4*)&g_eap[pos+4] = v1;
  g_eap[pos+8] = pr[8];
}

// ---------------- per-head h = x @ W (f32x2), fused alpha projections ----------------
__global__ void k_head_h(const float* __restrict__ gat_W, const float* __restrict__ gat_a){
  __shared__ float sx[16*EMB];
  __shared__ float sw[EMB*DOUT];
  int head = blockIdx.y;
  int n0 = blockIdx.x*16;
  int t = threadIdx.x;
  const float* W = gat_W + (size_t)head*EMB*DOUT;
  ((float4*)sx)[t] = ((const float4*)(g_x + (size_t)n0*EMB))[t];
  #pragma unroll
  for(int i = 0; i < 4; i++)
    ((float4*)sw)[t + 256*i] = ((const float4*)W)[t + 256*i];
  __syncthreads();
  int nn = t >> 4;
  int j0 = (t & 15)*4;
  u64t acc01 = 0, acc23 = 0;
  #pragma unroll
  for(int k = 0; k < EMB; k++){
    float xv = sx[nn*EMB + k];
    u64t xv2 = pack2(xv, xv);
    acc01 = ffma2(xv2, *(const u64t*)&sw[k*DOUT + j0],     acc01);
    acc23 = ffma2(xv2, *(const u64t*)&sw[k*DOUT + j0 + 2], acc23);
  }
  float2 f01 = unpack2(acc01), f23 = unpack2(acc23);
  float4 acc = {f01.x, f01.y, f23.x, f23.y};
  int n = n0 + nn;
  *(float4*)&g_h[((size_t)head*NNODES + n)*DOUT + j0] = acc;
  const float* a = gat_a + head*192;
  float ps = acc.x*a[j0] + acc.y*a[j0+1] + acc.z*a[j0+2] + acc.w*a[j0+3];
  float pt = acc.x*a[64+j0] + acc.y*a[64+j0+1] + acc.z*a[64+j0+2] + acc.w*a[64+j0+3];
  #pragma unroll
  for(int o = 8; o >= 1; o >>= 1){
    ps += __shfl_xor_sync(0xffffffffu, ps, o);
    pt += __shfl_xor_sync(0xffffffffu, pt, o);
  }
  if((t & 15) == 0){
    g_asrc[n*16 + head] = ps;
    g_atgt[n*16 + head] = pt;
  }
}

// ---------------- FUSED score+exp+denom+aggregation, layer 1 (warp per node) --------
__global__ void k_fagg1(){
  int warp = (blockIdx.x*blockDim.x + threadIdx.x) >> 5;
  int lane = threadIdx.x & 31;
  if(warp >= NNODES) return;
  int n = warp;
  int r0 = g_row[n], r1 = g_row[n+1];
  float asl = (lane < 8) ? g_asrc[n*16 + lane] : 0.f;
  float num0[8], num1[8];
  #pragma unroll
  for(int h = 0; h < 8; h++){ num0[h] = 0.f; num1[h] = 0.f; }
  float den = 0.f;
  #pragma unroll 2
  for(int pos = r0; pos < r1; pos++){
    int tg = g_tgtc[pos];
    float sc = 0.f;
    if(lane < 8) sc = asl + g_atgt[tg*16 + lane] + g_eap[(size_t)pos*16 + lane];
    float ev = __expf(lrelu(sc));
    if(lane < 8) den += ev;
    #pragma unroll
    for(int h = 0; h < 8; h++){
      float w = __shfl_sync(0xffffffffu, ev, h);
      const float* p = g_h + ((size_t)h*NNODES + tg)*DOUT;
      num0[h] += w*p[lane];
      num1[h] += w*p[lane+32];
    }
  }
  #pragma unroll
  for(int h = 0; h < 8; h++){
    float dh = __shfl_sync(0xffffffffu, den, h);
    float rd = 1.f/(dh + 1e-16f);
    float* o = g_hp + ((size_t)h*NNODES + n)*DOUT;
    o[lane]    = num0[h]*rd;
    o[lane+32] = num1[h]*rd;
  }
}

// ---------------- final layer h2 = elu(elu(hp_concat)) @ out_W (f32x2) ----------------
__global__ void k_out_h(const float* __restrict__ out_W, const float* __restrict__ out_a){
  __shared__ float sx[16*EMB];
  __shared__ float sw[EMB*DOUT];
  int n0 = blockIdx.x*16;
  int t = threadIdx.x;
  int nn = t >> 4;
  int j0 = (t & 15)*4;
  u64t acc01 = 0, acc23 = 0;
  for(int c = 0; c < NHEADS; c++){
    __syncthreads();
    float4 xv4 = ((const float4*)(g_hp + ((size_t)c*NNODES + n0)*DOUT))[t];
    xv4.x = eluf(eluf(xv4.x)); xv4.y = eluf(eluf(xv4.y));
    xv4.z = eluf(eluf(xv4.z)); xv4.w = eluf(eluf(xv4.w));
    ((float4*)sx)[t] = xv4;
    #pragma unroll
    for(int i = 0; i < 4; i++)
      ((float4*)sw)[t + 256*i] = ((const float4*)(out_W + (size_t)c*EMB*DOUT))[t + 256*i];
    __syncthreads();
    #pragma unroll
    for(int k = 0; k < EMB; k++){
      float xv = sx[nn*EMB + k];
      u64t xv2 = pack2(xv, xv);
      acc01 = ffma2(xv2, *(const u64t*)&sw[k*DOUT + j0],     acc01);
      acc23 = ffma2(xv2, *(const u64t*)&sw[k*DOUT + j0 + 2], acc23);
    }
  }
  float2 f01 = unpack2(acc01), f23 = unpack2(acc23);
  float4 acc = {f01.x, f01.y, f23.x, f23.y};
  int n = n0 + nn;
  *(float4*)&g_h2[(size_t)n*DOUT + j0] = acc;
  float ps = acc.x*out_a[j0] + acc.y*out_a[j0+1] + acc.z*out_a[j0+2] + acc.w*out_a[j0+3];
  float pt = acc.x*out_a[64+j0] + acc.y*out_a[64+j0+1] + acc.z*out_a[64+j0+2] + acc.w*out_a[64+j0+3];
  #pragma unroll
  for(int o = 8; o >= 1; o >>= 1){
    ps += __shfl_xor_sync(0xffffffffu, ps, o);
    pt += __shfl_xor_sync(0xffffffffu, pt, o);
  }
  if((t & 15) == 0){
    g_asrc[n*16 + 8] = ps;
    g_atgt[n*16 + 8] = pt;
  }
}

// ---------------- FUSED layer 2 aggregation ----------------
__global__ void k_fagg2(){
  int warp = (blockIdx.x*blockDim.x + threadIdx.x) >> 5;
  int lane = threadIdx.x & 31;
  if(warp >= NNODES) return;
  int n = warp;
  int r0 = g_row[n], r1 = g_row[n+1];
  float as2 = g_asrc[n*16 + 8];
  float num0 = 0.f, num1 = 0.f, den = 0.f;
  #pragma unroll 2
  for(int pos = r0; pos < r1; pos++){
    int tg = g_tgtc[pos];
    float sc = as2 + g_atgt[tg*16 + 8] + g_eap[(size_t)pos*16 + 8];
    float ev = __expf(lrelu(sc));
    den += ev;
    const float* p = g_h2 + (size_t)tg*DOUT;
    num0 += ev*p[lane];
    num1 += ev*p[lane+32];
  }
  float rd = 1.f/(den + 1e-16f);
  g_hp2[(size_t)n*DOUT + lane]    = num0*rd;
  g_hp2[(size_t)n*DOUT + lane+32] = num1*rd;
}

// ---------------- out = log_softmax(elu(hp2)) ----------------
__global__ void k_logsoftmax(float* __restrict__ out){
  int gid = blockIdx.x*blockDim.x + threadIdx.x;
  int n = gid >> 5;
  int lane = gid & 31;
  if(n >= NNODES) return;
  float v0 = eluf(g_hp2[(size_t)n*DOUT + lane]);
  float v1 = eluf(g_hp2[(size_t)n*DOUT + lane + 32]);
  float m = fmaxf(v0, v1);
  #pragma unroll
  for(int o = 16; o >= 1; o >>= 1) m = fmaxf(m, __shfl_xor_sync(0xffffffffu, m, o));
  float s = expf(v0 - m) + expf(v1 - m);
  #pragma unroll
  for(int o = 16; o >= 1; o >>= 1) s += __shfl_xor_sync(0xffffffffu, s, o);
  float l = logf(s);
  out[(size_t)n*DOUT + lane]      = v0 - m - l;
  out[(size_t)n*DOUT + lane + 32] = v1 - m - l;
}

// ---------------- launcher ----------------
extern "C" void kernel_launch(void* const* d_in, const int* in_sizes, int n_in,
                              void* d_out, int out_size){
  const float *X=0, *EA=0, *w_node=0, *w_edge=0, *gatW=0, *gata=0, *outW=0, *outa=0;
  const void* ei = 0;
  const float* v64[8]; int n64 = 0; int nbig = 0;
  for(int i = 0; i < n_in; i++){
    switch(in_sizes[i]){
      case 800000:  X    = (const float*)d_in[i]; break;
      case 8000000: EA   = (const float*)d_in[i]; break;
      case 2000000: ei   = d_in[i]; break;
      case 1024:    w_node = (const float*)d_in[i]; break;
      case 512:     w_edge = (const float*)d_in[i]; break;
      case 1536:    gata = (const float*)d_in[i]; break;
      case 192:     outa = (const float*)d_in[i]; break;
      case 32768:   if(nbig++ == 0) gatW = (const float*)d_in[i];
                    else            outW = (const float*)d_in[i];
                    break;
      case 64:      if(n64 < 8) v64[n64++] = (const float*)d_in[i]; break;
      default: break;
    }
  }
  const float* b_node = v64[0]; const float* g_node = v64[1]; const float* beta_node = v64[2];
  const float* b_edge = v64[3]; const float* g_edge = v64[4]; const float* beta_edge = v64[5];

  // CSR build
  k_detect<<<1, 1>>>(ei);
  k_zero_cnt<<<(NNODES + 255)/256, 256>>>();
  k_convert<<<(NEDGES + 255)/256, 256>>>(ei);
  k_scan1<<<SCANB, 1024>>>();
  k_scan2<<<1, 32>>>();
  k_scan3<<<SCANB, 1024>>>();
  k_scatter<<<(NEDGES + 255)/256, 256>>>();

  // MLPs + projections
  k_node_mlp<<<(NNODES + 255)/256, 256>>>(X, w_node, b_node, g_node, beta_node);
  k_edge_mlp<<<(NEDGES + 127)/128, 128>>>(EA, w_edge, b_edge, g_edge, beta_edge, gata, outa);
  k_head_h<<<dim3(NNODES/16, NHEADS, 1), 256>>>(gatW, gata);

  // layer 1: fully fused softmax-aggregation
  k_fagg1<<<(NNODES*32 + 255)/256, 256>>>();

  // layer 2
  k_out_h<<<NNODES/16, 256>>>(outW, outa);
  k_fagg2<<<(NNODES*32 + 255)/256, 256>>>();

  k_logsoftmax<<<(NNODES*32 + 255)/256, 256>>>((float*)d_out);
}

// round 5
// speedup vs baseline: 2.0603x; 1.4248x over previous
#include <cuda_runtime.h>
#include <math.h>

#define NNODES 50000
#define NEDGES 1000000
#define NDIM   16
#define EMB    64
#define DOUT   64
#define NHEADS 8
#define EADIM  8
#define SLOPE  0.01f
#define LN_EPS 1e-5f
#define SCANB  49    // ceil(50000/1024)
#define NPB    80    // nodes per block in GEMM kernels (50000 = 625*80)

// ---------------- scratch ----------------
__device__ __align__(128) float g_x[(size_t)NNODES*EMB];
__device__ __align__(128) float g_eap8[(size_t)NEDGES*8];   // per-edge head-projections, CSR order
__device__ __align__(128) float g_eap2[NEDGES];             // layer-2 projection, CSR order
__device__ __align__(128) float g_h[(size_t)NHEADS*NNODES*DOUT];
__device__ __align__(128) float g_hp[(size_t)NHEADS*NNODES*DOUT];
__device__ __align__(128) float g_h2[(size_t)NNODES*DOUT];
__device__ __align__(128) float g_hp2[(size_t)NNODES*DOUT];
__device__ __align__(128) float g_exp[(size_t)NHEADS*NEDGES];
__device__ __align__(128) float g_asrc8[NNODES*8];
__device__ __align__(128) float g_atgt8[NNODES*8];
__device__ __align__(128) float g_asrc2[NNODES];
__device__ __align__(128) float g_atgt2[NNODES];
__device__ __align__(128) float g_rden[NNODES*8];
__device__ __align__(128) int g_src[NEDGES];
__device__ __align__(128) int g_tgt[NEDGES];
__device__ __align__(128) int g_tgtc[NEDGES];
__device__ __align__(128) int g_row[NNODES+1];
__device__ __align__(128) int g_cur[NNODES];
__device__ __align__(128) int g_cnt[NNODES];
__device__ __align__(128) int g_part[64];
__device__ int g_flag;

__device__ __forceinline__ float eluf(float x){ return x > 0.f ? x : expm1f(x); }
__device__ __forceinline__ float lrelu(float x){ return x >= 0.f ? x : SLOPE * x; }

typedef unsigned long long u64t;
__device__ __forceinline__ u64t pack2(float lo, float hi){
  u64t r; asm("mov.b64 %0, {%1,%2};" : "=l"(r) : "f"(lo), "f"(hi)); return r;
}
__device__ __forceinline__ u64t ffma2(u64t a, u64t b, u64t c){
  u64t d; asm("fma.rn.f32x2 %0, %1, %2, %3;" : "=l"(d) : "l"(a), "l"(b), "l"(c)); return d;
}
__device__ __forceinline__ float2 unpack2(u64t v){
  float2 f; asm("mov.b64 {%0,%1}, %2;" : "=f"(f.x), "=f"(f.y) : "l"(v)); return f;
}

// ---------------- index dtype detection ----------------
__global__ void k_detect(const void* ei){
  const long long* p = (const long long*)ei;
  int is64 = 1;
  for(int i = 0; i < 64; i++){
    long long v = p[i];
    if(v < 0 || v >= 4294967296LL) is64 = 0;
  }
  g_flag = is64;
}

__global__ void k_zero_cnt(){
  int i = blockIdx.x*blockDim.x + threadIdx.x;
  if(i < NNODES) g_cnt[i] = 0;
}

__global__ void k_convert(const void* ei){
  int e = blockIdx.x*blockDim.x + threadIdx.x;
  if(e >= NEDGES) return;
  int s, t;
  if(g_flag){
    const long long* p = (const long long*)ei;
    s = (int)p[e]; t = (int)p[NEDGES + e];
  } else {
    const int* p = (const int*)ei;
    s = p[e]; t = p[NEDGES + e];
  }
  g_src[e] = s; g_tgt[e] = t;
  atomicAdd(&g_cnt[s], 1);
}

// ---------------- parallel scan ----------------
__global__ void k_scan1(){
  __shared__ int swarp[32];
  int i = blockIdx.x*1024 + threadIdx.x;
  int lane = threadIdx.x & 31, wid = threadIdx.x >> 5;
  int v = (i < NNODES) ? g_cnt[i] : 0;
  int x = v;
  #pragma unroll
  for(int o = 1; o < 32; o <<= 1){
    int y = __shfl_up_sync(0xffffffffu, x, o);
    if(lane >= o) x += y;
  }
  if(lane == 31) swarp[wid] = x;
  __syncthreads();
  if(wid == 0){
    int s = swarp[lane];
    #pragma unroll
    for(int o = 1; o < 32; o <<= 1){
      int y = __shfl_up_sync(0xffffffffu, s, o);
      if(lane >= o) s += y;
    }
    swarp[lane] = s;
  }
  __syncthreads();
  int base = wid ? swarp[wid-1] : 0;
  int incl = base + x;
  if(i < NNODES) g_row[i] = incl - v;
  if(threadIdx.x == 1023) g_part[blockIdx.x] = incl;
}

__global__ void k_scan2(){
  if(threadIdx.x == 0){
    int s = 0;
    for(int i = 0; i < SCANB; i++){ int v = g_part[i]; g_part[i] = s; s += v; }
  }
}

__global__ void k_scan3(){
  int i = blockIdx.x*1024 + threadIdx.x;
  if(i < NNODES){
    int r = g_row[i] + g_part[blockIdx.x];
    g_row[i] = r; g_cur[i] = r;
  }
  if(i == 0) g_row[NNODES] = NEDGES;
}

// ---------------- node MLP ----------------
__global__ void k_node_mlp(const float* __restrict__ X, const float* __restrict__ w,
                           const float* __restrict__ b, const float* __restrict__ g,
                           const float* __restrict__ beta){
  __shared__ float sw[NDIM*EMB];
  __shared__ float sb[EMB], sg[EMB], sbt[EMB];
  for(int i = threadIdx.x; i < NDIM*EMB; i += blockDim.x) sw[i] = w[i];
  for(int i = threadIdx.x; i < EMB; i += blockDim.x){ sb[i]=b[i]; sg[i]=g[i]; sbt[i]=beta[i]; }
  __syncthreads();
  int n = blockIdx.x*blockDim.x + threadIdx.x;
  if(n >= NNODES) return;
  float xin[NDIM];
  const float4* px = (const float4*)(X + (size_t)n*NDIM);
  #pragma unroll
  for(int q = 0; q < 4; q++){
    float4 v = px[q];
    xin[q*4+0]=v.x; xin[q*4+1]=v.y; xin[q*4+2]=v.z; xin[q*4+3]=v.w;
  }
  u64t xk2[NDIM];
  #pragma unroll
  for(int k = 0; k < NDIM; k++) xk2[k] = pack2(xin[k], xin[k]);
  float y[EMB]; float sum = 0.f;
  #pragma unroll
  for(int jp = 0; jp < EMB/2; jp++){
    u64t acc = pack2(sb[2*jp], sb[2*jp+1]);
    #pragma unroll
    for(int k = 0; k < NDIM; k++)
      acc = ffma2(xk2[k], *(const u64t*)&sw[k*EMB + 2*jp], acc);
    float2 f = unpack2(acc);
    y[2*jp] = f.x; y[2*jp+1] = f.y;
    sum += f.x + f.y;
  }
  float mu = sum * (1.f/EMB);
  float vs = 0.f;
  #pragma unroll
  for(int j = 0; j < EMB; j++){ float d = y[j]-mu; vs += d*d; }
  float inv = rsqrtf(vs*(1.f/EMB) + LN_EPS);
  #pragma unroll
  for(int j = 0; j < EMB; j++){
    float v = (y[j]-mu)*inv*sg[j] + sbt[j];
    g_x[(size_t)n*EMB + j] = fmaxf(v, 0.f);
  }
}

// ---------------- edge MLP + 9 projections + fused CSR scatter ----------------
__global__ void k_edge_mlp(const float* __restrict__ EA, const float* __restrict__ w,
                           const float* __restrict__ b, const float* __restrict__ g,
                           const float* __restrict__ beta, const float* __restrict__ gat_a,
                           const float* __restrict__ out_a){
  __shared__ float sw[EADIM*EMB];
  __shared__ float sb[EMB], sg[EMB], sbt[EMB];
  __shared__ float sa[9][EMB];
  for(int i = threadIdx.x; i < EADIM*EMB; i += blockDim.x) sw[i] = w[i];
  for(int i = threadIdx.x; i < EMB; i += blockDim.x){ sb[i]=b[i]; sg[i]=g[i]; sbt[i]=beta[i]; }
  for(int i = threadIdx.x; i < 9*EMB; i += blockDim.x){
    int p = i/EMB, j = i%EMB;
    sa[p][j] = (p < 8) ? gat_a[p*192 + 128 + j] : out_a[128 + j];
  }
  __syncthreads();
  int e = blockIdx.x*blockDim.x + threadIdx.x;
  if(e >= NEDGES) return;
  const float4* pe = (const float4*)(EA + (size_t)e*EADIM);
  float4 a0 = pe[0], a1 = pe[1];
  float xin[EADIM] = {a0.x,a0.y,a0.z,a0.w,a1.x,a1.y,a1.z,a1.w};
  u64t xk2[EADIM];
  #pragma unroll
  for(int k = 0; k < EADIM; k++) xk2[k] = pack2(xin[k], xin[k]);
  float y[EMB]; float sum = 0.f;
  #pragma unroll
  for(int jp = 0; jp < EMB/2; jp++){
    u64t acc = pack2(sb[2*jp], sb[2*jp+1]);
    #pragma unroll
    for(int k = 0; k < EADIM; k++)
      acc = ffma2(xk2[k], *(const u64t*)&sw[k*EMB + 2*jp], acc);
    float2 f = unpack2(acc);
    y[2*jp] = f.x; y[2*jp+1] = f.y;
    sum += f.x + f.y;
  }
  float mu = sum*(1.f/EMB);
  float vs = 0.f;
  #pragma unroll
  for(int j = 0; j < EMB; j++){ float d = y[j]-mu; vs += d*d; }
  float inv = rsqrtf(vs*(1.f/EMB) + LN_EPS);
  u64t y2[EMB/2];
  #pragma unroll
  for(int j = 0; j < EMB; j += 2){
    float v0 = fmaxf((y[j]-mu)*inv*sg[j] + sbt[j], 0.f);
    float v1 = fmaxf((y[j+1]-mu)*inv*sg[j+1] + sbt[j+1], 0.f);
    y2[j/2] = pack2(v0, v1);
  }
  float pr[9];
  #pragma unroll
  for(int p = 0; p < 9; p++){
    u64t acc = 0;
    #pragma unroll
    for(int jp = 0; jp < EMB/2; jp++)
      acc = ffma2(y2[jp], *(const u64t*)&sa[p][2*jp], acc);
    float2 f = unpack2(acc);
    pr[p] = f.x + f.y;
  }
  // fused CSR scatter
  int s = g_src[e];
  int pos = atomicAdd(&g_cur[s], 1);
  g_tgtc[pos] = g_tgt[e];
  float4 v0 = {pr[0],pr[1],pr[2],pr[3]};
  float4 v1 = {pr[4],pr[5],pr[6],pr[7]};
  *(float4*)&g_eap8[(size_t)pos*8]   = v0;
  *(float4*)&g_eap8[(size_t)pos*8+4] = v1;
  g_eap2[pos] = pr[8];
}

// ---------------- per-head h = x @ W (80 nodes/block, W reused) ----------------
__global__ void k_head_h(const float* __restrict__ gat_W, const float* __restrict__ gat_a){
  __shared__ float sx[NPB*EMB];   // 20KB
  __shared__ float sw[EMB*DOUT];  // 16KB
  int head = blockIdx.y;
  int n0 = blockIdx.x*NPB;
  int t = threadIdx.x;
  const float* W = gat_W + (size_t)head*EMB*DOUT;
  #pragma unroll
  for(int i = 0; i < 4; i++)
    ((float4*)sw)[t + 256*i] = ((const float4*)W)[t + 256*i];
  const float4* px = (const float4*)(g_x + (size_t)n0*EMB);
  #pragma unroll
  for(int i = 0; i < 5; i++)
    ((float4*)sx)[t + 256*i] = px[t + 256*i];
  __syncthreads();
  int nn = t >> 4;
  int j0 = (t & 15)*4;
  const float* a = gat_a + head*192;
  float aj0 = a[j0],    aj1 = a[j0+1],    aj2 = a[j0+2],    aj3 = a[j0+3];
  float bj0 = a[64+j0], bj1 = a[64+j0+1], bj2 = a[64+j0+2], bj3 = a[64+j0+3];
  #pragma unroll
  for(int g = 0; g < 5; g++){
    u64t acc01 = 0, acc23 = 0;
    const float* xr = &sx[(g*16 + nn)*EMB];
    #pragma unroll
    for(int k = 0; k < EMB; k++){
      float xv = xr[k];
      u64t xv2 = pack2(xv, xv);
      acc01 = ffma2(xv2, *(const u64t*)&sw[k*DOUT + j0],     acc01);
      acc23 = ffma2(xv2, *(const u64t*)&sw[k*DOUT + j0 + 2], acc23);
    }
    float2 f01 = unpack2(acc01), f23 = unpack2(acc23);
    float4 acc = {f01.x, f01.y, f23.x, f23.y};
    int n = n0 + g*16 + nn;
    *(float4*)&g_h[((size_t)head*NNODES + n)*DOUT + j0] = acc;
    float ps = acc.x*aj0 + acc.y*aj1 + acc.z*aj2 + acc.w*aj3;
    float pt = acc.x*bj0 + acc.y*bj1 + acc.z*bj2 + acc.w*bj3;
    #pragma unroll
    for(int o = 8; o >= 1; o >>= 1){
      ps += __shfl_xor_sync(0xffffffffu, ps, o);
      pt += __shfl_xor_sync(0xffffffffu, pt, o);
    }
    if((t & 15) == 0){
      g_asrc8[n*8 + head] = ps;
      g_atgt8[n*8 + head] = pt;
    }
  }
}

// ---------------- score+exp+denom for 8 heads (warp per node) ----------------
__global__ void k_sed1(){
  int warp = (blockIdx.x*blockDim.x + threadIdx.x) >> 5;
  int lane = threadIdx.x & 31;
  if(warp >= NNODES) return;
  int n = warp;
  int r0 = g_row[n], r1 = g_row[n+1];
  float4 as0 = *(const float4*)&g_asrc8[n*8];
  float4 as1 = *(const float4*)&g_asrc8[n*8+4];
  float acc[8] = {0.f,0.f,0.f,0.f,0.f,0.f,0.f,0.f};
  for(int pos = r0 + lane; pos < r1; pos += 32){
    int tg = g_tgtc[pos];
    float4 e0 = *(const float4*)&g_eap8[(size_t)pos*8];
    float4 e1 = *(const float4*)&g_eap8[(size_t)pos*8+4];
    float4 t0 = *(const float4*)&g_atgt8[tg*8];
    float4 t1 = *(const float4*)&g_atgt8[tg*8+4];
    float ev;
    ev = __expf(lrelu(as0.x + t0.x + e0.x)); g_exp[(size_t)0*NEDGES+pos] = ev; acc[0] += ev;
    ev = __expf(lrelu(as0.y + t0.y + e0.y)); g_exp[(size_t)1*NEDGES+pos] = ev; acc[1] += ev;
    ev = __expf(lrelu(as0.z + t0.z + e0.z)); g_exp[(size_t)2*NEDGES+pos] = ev; acc[2] += ev;
    ev = __expf(lrelu(as0.w + t0.w + e0.w)); g_exp[(size_t)3*NEDGES+pos] = ev; acc[3] += ev;
    ev = __expf(lrelu(as1.x + t1.x + e1.x)); g_exp[(size_t)4*NEDGES+pos] = ev; acc[4] += ev;
    ev = __expf(lrelu(as1.y + t1.y + e1.y)); g_exp[(size_t)5*NEDGES+pos] = ev; acc[5] += ev;
    ev = __expf(lrelu(as1.z + t1.z + e1.z)); g_exp[(size_t)6*NEDGES+pos] = ev; acc[6] += ev;
    ev = __expf(lrelu(as1.w + t1.w + e1.w)); g_exp[(size_t)7*NEDGES+pos] = ev; acc[7] += ev;
  }
  #pragma unroll
  for(int h = 0; h < 8; h++){
    float a = acc[h];
    #pragma unroll
    for(int o = 16; o >= 1; o >>= 1) a += __shfl_xor_sync(0xffffffffu, a, o);
    acc[h] = a;
  }
  if(lane == 0){
    #pragma unroll
    for(int h = 0; h < 8; h++)
      g_rden[n*8 + h] = 1.f/(acc[h] + 1e-16f);
  }
}

// ---------------- CSR aggregation: warp per (node, head), float2 gathers --------
__global__ void k_agg(){
  int h = blockIdx.y;
  int warp = (blockIdx.x*blockDim.x + threadIdx.x) >> 5;
  int lane = threadIdx.x & 31;
  if(warp >= NNODES) return;
  int n = warp;
  int r0 = g_row[n], r1 = g_row[n+1];
  float rd = g_rden[n*8 + h];
  const float* __restrict__ hs = g_h + (size_t)h*NNODES*DOUT;
  const float* __restrict__ ex = g_exp + (size_t)h*NEDGES;
  float ax = 0.f, ay = 0.f;
  int pos = r0;
  for(; pos + 1 < r1; pos += 2){
    int tg0 = g_tgtc[pos];
    int tg1 = g_tgtc[pos+1];
    float w0 = ex[pos];
    float w1 = ex[pos+1];
    float2 v0 = ((const float2*)(hs + (size_t)tg0*DOUT))[lane];
    float2 v1 = ((const float2*)(hs + (size_t)tg1*DOUT))[lane];
    ax += w0*v0.x + w1*v1.x;
    ay += w0*v0.y + w1*v1.y;
  }
  if(pos < r1){
    int tg = g_tgtc[pos];
    float w = ex[pos];
    float2 v = ((const float2*)(hs + (size_t)tg*DOUT))[lane];
    ax += w*v.x; ay += w*v.y;
  }
  float2 o = {ax*rd, ay*rd};
  ((float2*)(g_hp + ((size_t)h*NNODES + n)*DOUT))[lane] = o;
}

// ---------------- final layer h2 = elu(elu(hp_concat)) @ out_W (80 nodes/block) ----
__global__ void k_out_h(const float* __restrict__ out_W, const float* __restrict__ out_a){
  __shared__ float sx[NPB*EMB];   // 20KB
  __shared__ float sw[EMB*DOUT];  // 16KB
  int n0 = blockIdx.x*NPB;
  int t = threadIdx.x;
  int nn = t >> 4;
  int j0 = (t & 15)*4;
  u64t a01[5], a23[5];
  #pragma unroll
  for(int g = 0; g < 5; g++){ a01[g] = 0; a23[g] = 0; }
  for(int c = 0; c < NHEADS; c++){
    __syncthreads();
    #pragma unroll
    for(int i = 0; i < 4; i++)
      ((float4*)sw)[t + 256*i] = ((const float4*)(out_W + (size_t)c*EMB*DOUT))[t + 256*i];
    const float4* hp4 = (const float4*)(g_hp + ((size_t)c*NNODES + n0)*DOUT);
    #pragma unroll
    for(int i = 0; i < 5; i++){
      float4 xv4 = hp4[t + 256*i];
      xv4.x = eluf(eluf(xv4.x)); xv4.y = eluf(eluf(xv4.y));
      xv4.z = eluf(eluf(xv4.z)); xv4.w = eluf(eluf(xv4.w));
      ((float4*)sx)[t + 256*i] = xv4;
    }
    __syncthreads();
    #pragma unroll
    for(int k = 0; k < EMB; k++){
      u64t w01 = *(const u64t*)&sw[k*DOUT + j0];
      u64t w23 = *(const u64t*)&sw[k*DOUT + j0 + 2];
      #pragma unroll
      for(int g = 0; g < 5; g++){
        float xv = sx[(g*16 + nn)*EMB + k];
        u64t xv2 = pack2(xv, xv);
        a01[g] = ffma2(xv2, w01, a01[g]);
        a23[g] = ffma2(xv2, w23, a23[g]);
      }
    }
  }
  #pragma unroll
  for(int g = 0; g < 5; g++){
    float2 f01 = unpack2(a01[g]), f23 = unpack2(a23[g]);
    float4 acc = {f01.x, f01.y, f23.x, f23.y};
    int n = n0 + g*16 + nn;
    *(float4*)&g_h2[(size_t)n*DOUT + j0] = acc;
    float ps = acc.x*out_a[j0] + acc.y*out_a[j0+1] + acc.z*out_a[j0+2] + acc.w*out_a[j0+3];
    float pt = acc.x*out_a[64+j0] + acc.y*out_a[64+j0+1] + acc.z*out_a[64+j0+2] + acc.w*out_a[64+j0+3];
    #pragma unroll
    for(int o = 8; o >= 1; o >>= 1){
      ps += __shfl_xor_sync(0xffffffffu, ps, o);
      pt += __shfl_xor_sync(0xffffffffu, pt, o);
    }
    if((t & 15) == 0){
      g_asrc2[n] = ps;
      g_atgt2[n] = pt;
    }
  }
}

// ---------------- fused layer-2 softmax aggregation ----------------
__global__ void k_fagg2(){
  int warp = (blockIdx.x*blockDim.x + threadIdx.x) >> 5;
  int lane = threadIdx.x & 31;
  if(warp >= NNODES) return;
  int n = warp;
  int r0 = g_row[n], r1 = g_row[n+1];
  float as2 = g_asrc2[n];
  float ax = 0.f, ay = 0.f, den = 0.f;
  int pos = r0;
  for(; pos + 1 < r1; pos += 2){
    int tg0 = g_tgtc[pos];
    int tg1 = g_tgtc[pos+1];
    float ev0 = __expf(lrelu(as2 + g_atgt2[tg0] + g_eap2[pos]));
    float ev1 = __expf(lrelu(as2 + g_atgt2[tg1] + g_eap2[pos+1]));
    den += ev0 + ev1;
    float2 v0 = ((const float2*)(g_h2 + (size_t)tg0*DOUT))[lane];
    float2 v1 = ((const float2*)(g_h2 + (size_t)tg1*DOUT))[lane];
    ax += ev0*v0.x + ev1*v1.x;
    ay += ev0*v0.y + ev1*v1.y;
  }
  if(pos < r1){
    int tg = g_tgtc[pos];
    float ev = __expf(lrelu(as2 + g_atgt2[tg] + g_eap2[pos]));
    den += ev;
    float2 v = ((const float2*)(g_h2 + (size_t)tg*DOUT))[lane];
    ax += ev*v.x; ay += ev*v.y;
  }
  float rd = 1.f/(den + 1e-16f);
  float2 o = {ax*rd, ay*rd};
  ((float2*)(g_hp2 + (size_t)n*DOUT))[lane] = o;
}

// ---------------- out = log_softmax(elu(hp2)) ----------------
__global__ void k_logsoftmax(float* __restrict__ out){
  int gid = blockIdx.x*blockDim.x + threadIdx.x;
  int n = gid >> 5;
  int lane = gid & 31;
  if(n >= NNODES) return;
  float v0 = eluf(g_hp2[(size_t)n*DOUT + lane]);
  float v1 = eluf(g_hp2[(size_t)n*DOUT + lane + 32]);
  float m = fmaxf(v0, v1);
  #pragma unroll
  for(int o = 16; o >= 1; o >>= 1) m = fmaxf(m, __shfl_xor_sync(0xffffffffu, m, o));
  float s = expf(v0 - m) + expf(v1 - m);
  #pragma unroll
  for(int o = 16; o >= 1; o >>= 1) s += __shfl_xor_sync(0xffffffffu, s, o);
  float l = logf(s);
  out[(size_t)n*DOUT + lane]      = v0 - m - l;
  out[(size_t)n*DOUT + lane + 32] = v1 - m - l;
}

// ---------------- launcher ----------------
extern "C" void kernel_launch(void* const* d_in, const int* in_sizes, int n_in,
                              void* d_out, int out_size){
  const float *X=0, *EA=0, *w_node=0, *w_edge=0, *gatW=0, *gata=0, *outW=0, *outa=0;
  const void* ei = 0;
  const float* v64[8]; int n64 = 0; int nbig = 0;
  for(int i = 0; i < n_in; i++){
    switch(in_sizes[i]){
      case 800000:  X    = (const float*)d_in[i]; break;
      case 8000000: EA   = (const float*)d_in[i]; break;
      case 2000000: ei   = d_in[i]; break;
      case 1024:    w_node = (const float*)d_in[i]; break;
      case 512:     w_edge = (const float*)d_in[i]; break;
      case 1536:    gata = (const float*)d_in[i]; break;
      case 192:     outa = (const float*)d_in[i]; break;
      case 32768:   if(nbig++ == 0) gatW = (const float*)d_in[i];
                    else            outW = (const float*)d_in[i];
                    break;
      case 64:      if(n64 < 8) v64[n64++] = (const float*)d_in[i]; break;
      default: break;
    }
  }
  const float* b_node = v64[0]; const float* g_node = v64[1]; const float* beta_node = v64[2];
  const float* b_edge = v64[3]; const float* g_edge = v64[4]; const float* beta_edge = v64[5];

  // CSR build
  k_detect<<<1, 1>>>(ei);
  k_zero_cnt<<<(NNODES + 255)/256, 256>>>();
  k_convert<<<(NEDGES + 255)/256, 256>>>(ei);
  k_scan1<<<SCANB, 1024>>>();
  k_scan2<<<1, 32>>>();
  k_scan3<<<SCANB, 1024>>>();

  // MLPs + projections (edge MLP also performs the CSR scatter)
  k_node_mlp<<<(NNODES + 255)/256, 256>>>(X, w_node, b_node, g_node, beta_node);
  k_edge_mlp<<<(NEDGES + 127)/128, 128>>>(EA, w_edge, b_edge, g_edge, beta_edge, gata, outa);
  k_head_h<<<dim3(NNODES/NPB, NHEADS, 1), 256>>>(gatW, gata);

  // layer 1
  k_sed1<<<(NNODES*32 + 255)/256, 256>>>();
  k_agg<<<dim3((NNODES*32 + 255)/256, NHEADS, 1), 256>>>();

  // layer 2
  k_out_h<<<NNODES/NPB, 256>>>(outW, outa);
  k_fagg2<<<(NNODES*32 + 255)/256, 256>>>();

  k_logsoftmax<<<(NNODES*32 + 255)/256, 256>>>((float*)d_out);
}

// round 6
// speedup vs baseline: 2.2866x; 1.1098x over previous
#include <cuda_runtime.h>
#include <cuda_fp16.h>
#include <math.h>

#define NNODES 50000
#define NEDGES 1000000
#define NDIM   16
#define EMB    64
#define DOUT   64
#define NHEADS 8
#define EADIM  8
#define SLOPE  0.01f
#define LN_EPS 1e-5f
#define SCANB  49    // ceil(50000/1024)
#define NPB    80    // nodes per block in GEMM kernels (50000 = 625*80)

// ---------------- scratch ----------------
__device__ __align__(128) float  g_x[(size_t)NNODES*EMB];
__device__ __align__(128) float  g_eap8[(size_t)NEDGES*8];   // per-edge head-projections, CSR order
__device__ __align__(128) float  g_eap2[NEDGES];             // layer-2 projection, CSR order
__device__ __align__(128) __half g_h16[(size_t)NNODES*512];  // h interleaved [n][head][64], fp16
__device__ __align__(128) __half g_hph[(size_t)NHEADS*NNODES*DOUT]; // hp [head][n][64], fp16
__device__ __align__(128) __half g_h2h[(size_t)NNODES*DOUT]; // layer-2 h, fp16
__device__ __align__(128) float  g_hp2[(size_t)NNODES*DOUT];
__device__ __align__(128) float  g_asrc8[NNODES*8];
__device__ __align__(128) float  g_atgt8[NNODES*8];
__device__ __align__(128) float  g_asrc2[NNODES];
__device__ __align__(128) float  g_atgt2[NNODES];
__device__ __align__(128) int g_src[NEDGES];
__device__ __align__(128) int g_tgt[NEDGES];
__device__ __align__(128) int g_tgtc[NEDGES];
__device__ __align__(128) int g_row[NNODES+1];
__device__ __align__(128) int g_cur[NNODES];
__device__ __align__(128) int g_cnt[NNODES];
__device__ __align__(128) int g_part[64];
__device__ int g_flag;

__device__ __forceinline__ float eluf(float x){ return x > 0.f ? x : expm1f(x); }
__device__ __forceinline__ float lrelu(float x){ return x >= 0.f ? x : SLOPE * x; }

typedef unsigned long long u64t;
__device__ __forceinline__ u64t pack2(float lo, float hi){
  u64t r; asm("mov.b64 %0, {%1,%2};" : "=l"(r) : "f"(lo), "f"(hi)); return r;
}
__device__ __forceinline__ u64t ffma2(u64t a, u64t b, u64t c){
  u64t d; asm("fma.rn.f32x2 %0, %1, %2, %3;" : "=l"(d) : "l"(a), "l"(b), "l"(c)); return d;
}
__device__ __forceinline__ float2 unpack2(u64t v){
  float2 f; asm("mov.b64 {%0,%1}, %2;" : "=f"(f.x), "=f"(f.y) : "l"(v)); return f;
}

// ---------------- index dtype detection ----------------
__global__ void k_detect(const void* ei){
  const long long* p = (const long long*)ei;
  int is64 = 1;
  for(int i = 0; i < 64; i++){
    long long v = p[i];
    if(v < 0 || v >= 4294967296LL) is64 = 0;
  }
  g_flag = is64;
}

__global__ void k_zero_cnt(){
  int i = blockIdx.x*blockDim.x + threadIdx.x;
  if(i < NNODES) g_cnt[i] = 0;
}

__global__ void k_convert(const void* ei){
  int e = blockIdx.x*blockDim.x + threadIdx.x;
  if(e >= NEDGES) return;
  int s, t;
  if(g_flag){
    const long long* p = (const long long*)ei;
    s = (int)p[e]; t = (int)p[NEDGES + e];
  } else {
    const int* p = (const int*)ei;
    s = p[e]; t = p[NEDGES + e];
  }
  g_src[e] = s; g_tgt[e] = t;
  atomicAdd(&g_cnt[s], 1);
}

// ---------------- parallel scan ----------------
__global__ void k_scan1(){
  __shared__ int swarp[32];
  int i = blockIdx.x*1024 + threadIdx.x;
  int lane = threadIdx.x & 31, wid = threadIdx.x >> 5;
  int v = (i < NNODES) ? g_cnt[i] : 0;
  int x = v;
  #pragma unroll
  for(int o = 1; o < 32; o <<= 1){
    int y = __shfl_up_sync(0xffffffffu, x, o);
    if(lane >= o) x += y;
  }
  if(lane == 31) swarp[wid] = x;
  __syncthreads();
  if(wid == 0){
    int s = swarp[lane];
    #pragma unroll
    for(int o = 1; o < 32; o <<= 1){
      int y = __shfl_up_sync(0xffffffffu, s, o);
      if(lane >= o) s += y;
    }
    swarp[lane] = s;
  }
  __syncthreads();
  int base = wid ? swarp[wid-1] : 0;
  int incl = base + x;
  if(i < NNODES) g_row[i] = incl - v;
  if(threadIdx.x == 1023) g_part[blockIdx.x] = incl;
}

__global__ void k_scan2(){
  if(threadIdx.x == 0){
    int s = 0;
    for(int i = 0; i < SCANB; i++){ int v = g_part[i]; g_part[i] = s; s += v; }
  }
}

__global__ void k_scan3(){
  int i = blockIdx.x*1024 + threadIdx.x;
  if(i < NNODES){
    int r = g_row[i] + g_part[blockIdx.x];
    g_row[i] = r; g_cur[i] = r;
  }
  if(i == 0) g_row[NNODES] = NEDGES;
}

// ---------------- node MLP ----------------
__global__ void k_node_mlp(const float* __restrict__ X, const float* __restrict__ w,
                           const float* __restrict__ b, const float* __restrict__ g,
                           const float* __restrict__ beta){
  __shared__ float sw[NDIM*EMB];
  __shared__ float sb[EMB], sg[EMB], sbt[EMB];
  for(int i = threadIdx.x; i < NDIM*EMB; i += blockDim.x) sw[i] = w[i];
  for(int i = threadIdx.x; i < EMB; i += blockDim.x){ sb[i]=b[i]; sg[i]=g[i]; sbt[i]=beta[i]; }
  __syncthreads();
  int n = blockIdx.x*blockDim.x + threadIdx.x;
  if(n >= NNODES) return;
  float xin[NDIM];
  const float4* px = (const float4*)(X + (size_t)n*NDIM);
  #pragma unroll
  for(int q = 0; q < 4; q++){
    float4 v = px[q];
    xin[q*4+0]=v.x; xin[q*4+1]=v.y; xin[q*4+2]=v.z; xin[q*4+3]=v.w;
  }
  u64t xk2[NDIM];
  #pragma unroll
  for(int k = 0; k < NDIM; k++) xk2[k] = pack2(xin[k], xin[k]);
  float y[EMB]; float sum = 0.f;
  #pragma unroll
  for(int jp = 0; jp < EMB/2; jp++){
    u64t acc = pack2(sb[2*jp], sb[2*jp+1]);
    #pragma unroll
    for(int k = 0; k < NDIM; k++)
      acc = ffma2(xk2[k], *(const u64t*)&sw[k*EMB + 2*jp], acc);
    float2 f = unpack2(acc);
    y[2*jp] = f.x; y[2*jp+1] = f.y;
    sum += f.x + f.y;
  }
  float mu = sum * (1.f/EMB);
  float vs = 0.f;
  #pragma unroll
  for(int j = 0; j < EMB; j++){ float d = y[j]-mu; vs += d*d; }
  float inv = rsqrtf(vs*(1.f/EMB) + LN_EPS);
  #pragma unroll
  for(int j = 0; j < EMB; j++){
    float v = (y[j]-mu)*inv*sg[j] + sbt[j];
    g_x[(size_t)n*EMB + j] = fmaxf(v, 0.f);
  }
}

// ---------------- edge MLP + 9 projections + fused CSR scatter ----------------
__global__ void k_edge_mlp(const float* __restrict__ EA, const float* __restrict__ w,
                           const float* __restrict__ b, const float* __restrict__ g,
                           const float* __restrict__ beta, const float* __restrict__ gat_a,
                           const float* __restrict__ out_a){
  __shared__ float sw[EADIM*EMB];
  __shared__ float sb[EMB], sg[EMB], sbt[EMB];
  __shared__ float sa[9][EMB];
  for(int i = threadIdx.x; i < EADIM*EMB; i += blockDim.x) sw[i] = w[i];
  for(int i = threadIdx.x; i < EMB; i += blockDim.x){ sb[i]=b[i]; sg[i]=g[i]; sbt[i]=beta[i]; }
  for(int i = threadIdx.x; i < 9*EMB; i += blockDim.x){
    int p = i/EMB, j = i%EMB;
    sa[p][j] = (p < 8) ? gat_a[p*192 + 128 + j] : out_a[128 + j];
  }
  __syncthreads();
  int e = blockIdx.x*blockDim.x + threadIdx.x;
  if(e >= NEDGES) return;
  const float4* pe = (const float4*)(EA + (size_t)e*EADIM);
  float4 a0 = pe[0], a1 = pe[1];
  float xin[EADIM] = {a0.x,a0.y,a0.z,a0.w,a1.x,a1.y,a1.z,a1.w};
  u64t xk2[EADIM];
  #pragma unroll
  for(int k = 0; k < EADIM; k++) xk2[k] = pack2(xin[k], xin[k]);
  float y[EMB]; float sum = 0.f;
  #pragma unroll
  for(int jp = 0; jp < EMB/2; jp++){
    u64t acc = pack2(sb[2*jp], sb[2*jp+1]);
    #pragma unroll
    for(int k = 0; k < EADIM; k++)
      acc = ffma2(xk2[k], *(const u64t*)&sw[k*EMB + 2*jp], acc);
    float2 f = unpack2(acc);
    y[2*jp] = f.x; y[2*jp+1] = f.y;
    sum += f.x + f.y;
  }
  float mu = sum*(1.f/EMB);
  float vs = 0.f;
  #pragma unroll
  for(int j = 0; j < EMB; j++){ float d = y[j]-mu; vs += d*d; }
  float inv = rsqrtf(vs*(1.f/EMB) + LN_EPS);
  u64t y2[EMB/2];
  #pragma unroll
  for(int j = 0; j < EMB; j += 2){
    float v0 = fmaxf((y[j]-mu)*inv*sg[j] + sbt[j], 0.f);
    float v1 = fmaxf((y[j+1]-mu)*inv*sg[j+1] + sbt[j+1], 0.f);
    y2[j/2] = pack2(v0, v1);
  }
  float pr[9];
  #pragma unroll
  for(int p = 0; p < 9; p++){
    u64t acc = 0;
    #pragma unroll
    for(int jp = 0; jp < EMB/2; jp++)
      acc = ffma2(y2[jp], *(const u64t*)&sa[p][2*jp], acc);
    float2 f = unpack2(acc);
    pr[p] = f.x + f.y;
  }
  int s = g_src[e];
  int pos = atomicAdd(&g_cur[s], 1);
  g_tgtc[pos] = g_tgt[e];
  float4 v0 = {pr[0],pr[1],pr[2],pr[3]};
  float4 v1 = {pr[4],pr[5],pr[6],pr[7]};
  *(float4*)&g_eap8[(size_t)pos*8]   = v0;
  *(float4*)&g_eap8[(size_t)pos*8+4] = v1;
  g_eap2[pos] = pr[8];
}

// ---------------- per-head h = x @ W -> fp16 interleaved [n][head][64] ----------------
__global__ void k_head_h(const float* __restrict__ gat_W, const float* __restrict__ gat_a){
  __shared__ float sx[NPB*EMB];   // 20KB
  __shared__ float sw[EMB*DOUT];  // 16KB
  int head = blockIdx.y;
  int n0 = blockIdx.x*NPB;
  int t = threadIdx.x;
  const float* W = gat_W + (size_t)head*EMB*DOUT;
  #pragma unroll
  for(int i = 0; i < 4; i++)
    ((float4*)sw)[t + 256*i] = ((const float4*)W)[t + 256*i];
  const float4* px = (const float4*)(g_x + (size_t)n0*EMB);
  #pragma unroll
  for(int i = 0; i < 5; i++)
    ((float4*)sx)[t + 256*i] = px[t + 256*i];
  __syncthreads();
  int nn = t >> 4;
  int j0 = (t & 15)*4;
  const float* a = gat_a + head*192;
  float aj0 = a[j0],    aj1 = a[j0+1],    aj2 = a[j0+2],    aj3 = a[j0+3];
  float bj0 = a[64+j0], bj1 = a[64+j0+1], bj2 = a[64+j0+2], bj3 = a[64+j0+3];
  #pragma unroll
  for(int g = 0; g < 5; g++){
    u64t acc01 = 0, acc23 = 0;
    const float* xr = &sx[(g*16 + nn)*EMB];
    #pragma unroll
    for(int k = 0; k < EMB; k++){
      float xv = xr[k];
      u64t xv2 = pack2(xv, xv);
      acc01 = ffma2(xv2, *(const u64t*)&sw[k*DOUT + j0],     acc01);
      acc23 = ffma2(xv2, *(const u64t*)&sw[k*DOUT + j0 + 2], acc23);
    }
    float2 f01 = unpack2(acc01), f23 = unpack2(acc23);
    float4 acc = {f01.x, f01.y, f23.x, f23.y};
    int n = n0 + g*16 + nn;
    __half2 lo = __floats2half2_rn(acc.x, acc.y);
    __half2 hi = __floats2half2_rn(acc.z, acc.w);
    uint2 u; u.x = *(unsigned*)&lo; u.y = *(unsigned*)&hi;
    *(uint2*)&g_h16[(size_t)n*512 + head*64 + j0] = u;
    float ps = acc.x*aj0 + acc.y*aj1 + acc.z*aj2 + acc.w*aj3;
    float pt = acc.x*bj0 + acc.y*bj1 + acc.z*bj2 + acc.w*bj3;
    #pragma unroll
    for(int o = 8; o >= 1; o >>= 1){
      ps += __shfl_xor_sync(0xffffffffu, ps, o);
      pt += __shfl_xor_sync(0xffffffffu, pt, o);
    }
    if((t & 15) == 0){
      g_asrc8[n*8 + head] = ps;
      g_atgt8[n*8 + head] = pt;
    }
  }
}

// ------- FUSED layer-1: score+exp+denom+aggregate, warp per node, fp16 gathers -------
__global__ void k_fagg1(){
  int warp = (blockIdx.x*blockDim.x + threadIdx.x) >> 5;
  int lane = threadIdx.x & 31;
  if(warp >= NNODES) return;
  int n = warp;
  int r0 = g_row[n], r1 = g_row[n+1];
  float asl = (lane < 8) ? g_asrc8[n*8 + lane] : 0.f;
  int h1 = lane >> 3;        // 0..3
  int h2 = h1 + 4;           // 4..7
  float acc[16];
  #pragma unroll
  for(int i = 0; i < 16; i++) acc[i] = 0.f;
  float den = 0.f;
  #pragma unroll 2
  for(int pos = r0; pos < r1; pos++){
    int tg = g_tgtc[pos];
    float sc = 0.f;
    if(lane < 8) sc = asl + g_atgt8[tg*8 + lane] + g_eap8[(size_t)pos*8 + lane];
    float ev = __expf(lrelu(sc));
    if(lane < 8) den += ev;
    float w1 = __shfl_sync(0xffffffffu, ev, h1);
    float w2 = __shfl_sync(0xffffffffu, ev, h2);
    const uint4* hp = (const uint4*)(g_h16 + (size_t)tg*512);
    uint4 va = hp[lane];        // head h1, j = (lane&7)*8 .. +8
    uint4 vb = hp[lane + 32];   // head h2, same j
    const __half2* pa = (const __half2*)&va;
    const __half2* pb = (const __half2*)&vb;
    #pragma unroll
    for(int q = 0; q < 4; q++){
      float2 fa = __half22float2(pa[q]);
      float2 fb = __half22float2(pb[q]);
      acc[2*q]     += w1*fa.x;  acc[2*q+1]   += w1*fa.y;
      acc[8+2*q]   += w2*fb.x;  acc[8+2*q+1] += w2*fb.y;
    }
  }
  float rd = 1.f/(den + 1e-16f);                 // valid on lanes 0..7
  float rd1 = __shfl_sync(0xffffffffu, rd, h1);
  float rd2 = __shfl_sync(0xffffffffu, rd, h2);
  int jj = (lane & 7)*8;
  uint4 o; __half2* po = (__half2*)&o;
  po[0] = __floats2half2_rn(acc[0]*rd1, acc[1]*rd1);
  po[1] = __floats2half2_rn(acc[2]*rd1, acc[3]*rd1);
  po[2] = __floats2half2_rn(acc[4]*rd1, acc[5]*rd1);
  po[3] = __floats2half2_rn(acc[6]*rd1, acc[7]*rd1);
  *(uint4*)&g_hph[((size_t)h1*NNODES + n)*64 + jj] = o;
  po[0] = __floats2half2_rn(acc[8]*rd2,  acc[9]*rd2);
  po[1] = __floats2half2_rn(acc[10]*rd2, acc[11]*rd2);
  po[2] = __floats2half2_rn(acc[12]*rd2, acc[13]*rd2);
  po[3] = __floats2half2_rn(acc[14]*rd2, acc[15]*rd2);
  *(uint4*)&g_hph[((size_t)h2*NNODES + n)*64 + jj] = o;
}

// ---------------- final layer h2 = elu(elu(hp_concat)) @ out_W (80 nodes/block) ----
__global__ void k_out_h(const float* __restrict__ out_W, const float* __restrict__ out_a){
  __shared__ float sx[NPB*EMB];   // 20KB
  __shared__ float sw[EMB*DOUT];  // 16KB
  int n0 = blockIdx.x*NPB;
  int t = threadIdx.x;
  int nn = t >> 4;
  int j0 = (t & 15)*4;
  u64t a01[5], a23[5];
  #pragma unroll
  for(int g = 0; g < 5; g++){ a01[g] = 0; a23[g] = 0; }
  for(int c = 0; c < NHEADS; c++){
    __syncthreads();
    #pragma unroll
    for(int i = 0; i < 4; i++)
      ((float4*)sw)[t + 256*i] = ((const float4*)(out_W + (size_t)c*EMB*DOUT))[t + 256*i];
    const uint2* hp = (const uint2*)(g_hph + ((size_t)c*NNODES + n0)*64);
    #pragma unroll
    for(int i = 0; i < 5; i++){
      uint2 u = hp[t + 256*i];
      float2 fa = __half22float2(*(const __half2*)&u.x);
      float2 fb = __half22float2(*(const __half2*)&u.y);
      float4 xv4 = {eluf(eluf(fa.x)), eluf(eluf(fa.y)), eluf(eluf(fb.x)), eluf(eluf(fb.y))};
      ((float4*)sx)[t + 256*i] = xv4;
    }
    __syncthreads();
    #pragma unroll
    for(int k = 0; k < EMB; k++){
      u64t w01 = *(const u64t*)&sw[k*DOUT + j0];
      u64t w23 = *(const u64t*)&sw[k*DOUT + j0 + 2];
      #pragma unroll
      for(int g = 0; g < 5; g++){
        float xv = sx[(g*16 + nn)*EMB + k];
        u64t xv2 = pack2(xv, xv);
        a01[g] = ffma2(xv2, w01, a01[g]);
        a23[g] = ffma2(xv2, w23, a23[g]);
      }
    }
  }
  #pragma unroll
  for(int g = 0; g < 5; g++){
    float2 f01 = unpack2(a01[g]), f23 = unpack2(a23[g]);
    float4 acc = {f01.x, f01.y, f23.x, f23.y};
    int n = n0 + g*16 + nn;
    __half2 lo = __floats2half2_rn(acc.x, acc.y);
    __half2 hi = __floats2half2_rn(acc.z, acc.w);
    uint2 u; u.x = *(unsigned*)&lo; u.y = *(unsigned*)&hi;
    *(uint2*)&g_h2h[(size_t)n*64 + j0] = u;
    float ps = acc.x*out_a[j0] + acc.y*out_a[j0+1] + acc.z*out_a[j0+2] + acc.w*out_a[j0+3];
    float pt = acc.x*out_a[64+j0] + acc.y*out_a[64+j0+1] + acc.z*out_a[64+j0+2] + acc.w*out_a[64+j0+3];
    #pragma unroll
    for(int o = 8; o >= 1; o >>= 1){
      ps += __shfl_xor_sync(0xffffffffu, ps, o);
      pt += __shfl_xor_sync(0xffffffffu, pt, o);
    }
    if((t & 15) == 0){
      g_asrc2[n] = ps;
      g_atgt2[n] = pt;
    }
  }
}

// ---------------- fused layer-2 softmax aggregation (fp16 gathers) ----------------
__global__ void k_fagg2(){
  int warp = (blockIdx.x*blockDim.x + threadIdx.x) >> 5;
  int lane = threadIdx.x & 31;
  if(warp >= NNODES) return;
  int n = warp;
  int r0 = g_row[n], r1 = g_row[n+1];
  float as2 = g_asrc2[n];
  float ax = 0.f, ay = 0.f, den = 0.f;
  int pos = r0;
  for(; pos + 1 < r1; pos += 2){
    int tg0 = g_tgtc[pos];
    int tg1 = g_tgtc[pos+1];
    float ev0 = __expf(lrelu(as2 + g_atgt2[tg0] + g_eap2[pos]));
    float ev1 = __expf(lrelu(as2 + g_atgt2[tg1] + g_eap2[pos+1]));
    den += ev0 + ev1;
    float2 v0 = __half22float2(((const __half2*)(g_h2h + (size_t)tg0*DOUT))[lane]);
    float2 v1 = __half22float2(((const __half2*)(g_h2h + (size_t)tg1*DOUT))[lane]);
    ax += ev0*v0.x + ev1*v1.x;
    ay += ev0*v0.y + ev1*v1.y;
  }
  if(pos < r1){
    int tg = g_tgtc[pos];
    float ev = __expf(lrelu(as2 + g_atgt2[tg] + g_eap2[pos]));
    den += ev;
    float2 v = __half22float2(((const __half2*)(g_h2h + (size_t)tg*DOUT))[lane]);
    ax += ev*v.x; ay += ev*v.y;
  }
  float rd = 1.f/(den + 1e-16f);
  float2 o = {ax*rd, ay*rd};
  ((float2*)(g_hp2 + (size_t)n*DOUT))[lane] = o;
}

// ---------------- out = log_softmax(elu(hp2)) ----------------
__global__ void k_logsoftmax(float* __restrict__ out){
  int gid = blockIdx.x*blockDim.x + threadIdx.x;
  int n = gid >> 5;
  int lane = gid & 31;
  if(n >= NNODES) return;
  float v0 = eluf(g_hp2[(size_t)n*DOUT + lane]);
  float v1 = eluf(g_hp2[(size_t)n*DOUT + lane + 32]);
  float m = fmaxf(v0, v1);
  #pragma unroll
  for(int o = 16; o >= 1; o >>= 1) m = fmaxf(m, __shfl_xor_sync(0xffffffffu, m, o));
  float s = expf(v0 - m) + expf(v1 - m);
  #pragma unroll
  for(int o = 16; o >= 1; o >>= 1) s += __shfl_xor_sync(0xffffffffu, s, o);
  float l = logf(s);
  out[(size_t)n*DOUT + lane]      = v0 - m - l;
  out[(size_t)n*DOUT + lane + 32] = v1 - m - l;
}

// ---------------- launcher ----------------
extern "C" void kernel_launch(void* const* d_in, const int* in_sizes, int n_in,
                              void* d_out, int out_size){
  const float *X=0, *EA=0, *w_node=0, *w_edge=0, *gatW=0, *gata=0, *outW=0, *outa=0;
  const void* ei = 0;
  const float* v64[8]; int n64 = 0; int nbig = 0;
  for(int i = 0; i < n_in; i++){
    switch(in_sizes[i]){
      case 800000:  X    = (const float*)d_in[i]; break;
      case 8000000: EA   = (const float*)d_in[i]; break;
      case 2000000: ei   = d_in[i]; break;
      case 1024:    w_node = (const float*)d_in[i]; break;
      case 512:     w_edge = (const float*)d_in[i]; break;
      case 1536:    gata = (const float*)d_in[i]; break;
      case 192:     outa = (const float*)d_in[i]; break;
      case 32768:   if(nbig++ == 0) gatW = (const float*)d_in[i];
                    else            outW = (const float*)d_in[i];
                    break;
      case 64:      if(n64 < 8) v64[n64++] = (const float*)d_in[i]; break;
      default: break;
    }
  }
  const float* b_node = v64[0]; const float* g_node = v64[1]; const float* beta_node = v64[2];
  const float* b_edge = v64[3]; const float* g_edge = v64[4]; const float* beta_edge = v64[5];

  // CSR build
  k_detect<<<1, 1>>>(ei);
  k_zero_cnt<<<(NNODES + 255)/256, 256>>>();
  k_convert<<<(NEDGES + 255)/256, 256>>>(ei);
  k_scan1<<<SCANB, 1024>>>();
  k_scan2<<<1, 32>>>();
  k_scan3<<<SCANB, 1024>>>();

  // MLPs + projections (edge MLP also performs the CSR scatter)
  k_node_mlp<<<(NNODES + 255)/256, 256>>>(X, w_node, b_node, g_node, beta_node);
  k_edge_mlp<<<(NEDGES + 127)/128, 128>>>(EA, w_edge, b_edge, g_edge, beta_edge, gata, outa);
  k_head_h<<<dim3(NNODES/NPB, NHEADS, 1), 256>>>(gatW, gata);

  // layer 1: fully fused softmax-aggregation (fp16 interleaved gathers)
  k_fagg1<<<(NNODES*32 + 255)/256, 256>>>();

  // layer 2
  k_out_h<<<NNODES/NPB, 256>>>(outW, outa);
  k_fagg2<<<(NNODES*32 + 255)/256, 256>>>();

  k_logsoftmax<<<(NNODES*32 + 255)/256, 256>>>((float*)d_out);
}